// round 11
// baseline (speedup 1.0000x reference)
#include <cuda_runtime.h>
#include <cuda_bf16.h>
#include <math.h>
#include <string.h>
#include <stdint.h>

#define NND   4096
#define KNBR  9
#define INC   32
#define OUTC  64
#define HID   128
#define SDIM  4096
#define KSPL  4
#define KLEN  (SDIM / KSPL)   // 1024
#define KC    64
#define AST   72              // smem row stride (bf16)

// ---------------- scratch (static device globals; no allocation) ----------------
__device__ float g_pd[2][8][NND][KNBR];
__device__ int   g_pi[2][8][NND][KNBR];
__device__ __nv_bfloat16 g_Sh[2][(size_t)NND * SDIM];   // 32 MB
__device__ __nv_bfloat16 g_Sl[2][(size_t)NND * SDIM];   // 32 MB
__device__ __nv_bfloat16 g_Wth[2][OUTC * SDIM];         // W^T hi [o][k]
__device__ __nv_bfloat16 g_Wtl[2][OUTC * SDIM];         // W^T lo [o][k]
__device__ float g_xjm[2][NND * INC];
__device__ float g_part[2][KSPL][NND][OUTC];

// ======================= KNN helpers ===========================================
__device__ __forceinline__ bool knn_less(float d, int i, float d2, int i2) {
    return (d < d2) || (d == d2 && i < i2);
}
__device__ __forceinline__ void knn_insert(float dist, int j, float bd[KNBR], int bi[KNBR]) {
    if (knn_less(dist, j, bd[KNBR - 1], bi[KNBR - 1])) {
        float cd = dist; int ci = j;
#pragma unroll
        for (int r = 0; r < KNBR; r++) {
            bool sw = knn_less(cd, ci, bd[r], bi[r]);
            float td = bd[r]; int ti = bi[r];
            if (sw) { bd[r] = cd; bi[r] = ci; cd = td; ci = ti; }
        }
    }
}
__device__ __forceinline__ void knn_merge_warp(float* md, int* mi, const float bd[KNBR],
                                               const int bi[KNBR], int lane,
                                               float* opd, int* opi, int q) {
#pragma unroll
    for (int r = 0; r < KNBR; r++) { md[lane * KNBR + r] = bd[r]; mi[lane * KNBR + r] = bi[r]; }
    __syncwarp();
    int p = 0;
    for (int r = 0; r < KNBR; r++) {
        float cd = (p < KNBR) ? md[lane * KNBR + p] : 3.4e38f;
        int   ci = (p < KNBR) ? mi[lane * KNBR + p] : 0x7FFFFFFF;
        float rd = cd; int ri = ci;
#pragma unroll
        for (int off = 16; off; off >>= 1) {
            float od = __shfl_xor_sync(0xFFFFFFFFu, rd, off);
            int   oi = __shfl_xor_sync(0xFFFFFFFFu, ri, off);
            if (knn_less(od, oi, rd, ri)) { rd = od; ri = oi; }
        }
        if (ci == ri && p < KNBR) p++;
        if (lane == 0) { opd[q * KNBR + r] = rd; opi[q * KNBR + r] = ri; }
    }
    __syncwarp();
}

// ---------------- KNN on pos: part-split, 4 candidates in flight per lane -------
#define PPART (NND / 2)
__global__ __launch_bounds__(256) void knn_pos_kernel(const float* __restrict__ pos) {
    __shared__ float smem[PPART * 3];
    int t = threadIdx.x, w = t >> 5, lane = t & 31;
    int q = blockIdx.x * 8 + w;
    int part = blockIdx.y;
    int base = part * PPART;

    for (int v = t; v < PPART * 3; v += 256) smem[v] = pos[base * 3 + v];
    __syncthreads();

    float q0 = pos[q * 3 + 0], q1 = pos[q * 3 + 1], q2 = pos[q * 3 + 2];
    float sqq = 0.f;
    sqq = fmaf(q0, q0, sqq); sqq = fmaf(q1, q1, sqq); sqq = fmaf(q2, q2, sqq);

    float bd[KNBR]; int bi[KNBR];
#pragma unroll
    for (int r = 0; r < KNBR; r++) { bd[r] = 3.4e38f; bi[r] = 0x7FFFFFFF; }

    for (int jl = lane; jl < PPART; jl += 128) {
        float dist[4];
#pragma unroll
        for (int u = 0; u < 4; u++) {
            int jj = jl + u * 32;
            float c0 = smem[jj * 3 + 0], c1 = smem[jj * 3 + 1], c2 = smem[jj * 3 + 2];
            float acc = 0.f;
            acc = fmaf(q0, c0, acc); acc = fmaf(q1, c1, acc); acc = fmaf(q2, c2, acc);
            float sqj = 0.f;
            sqj = fmaf(c0, c0, sqj); sqj = fmaf(c1, c1, sqj); sqj = fmaf(c2, c2, sqj);
            dist[u] = (sqq + sqj) - 2.0f * acc;
        }
#pragma unroll
        for (int u = 0; u < 4; u++) knn_insert(dist[u], base + jl + u * 32, bd, bi);
    }
    __syncthreads();

    float* md = smem + (size_t)w * 288;
    int*   mi = (int*)(smem + 8 * 288) + (size_t)w * 288;
    knn_merge_warp(md, mi, bd, bi, lane, &g_pd[0][part][0][0], &g_pi[0][part][0][0], q);
}

// ---------------- KNN on x: two-phase tile kernel, 8 candidate parts ------------
#define CT 128
#define FPART2 (NND / 8)
__global__ __launch_bounds__(256) void knn_feat_kernel(const float* __restrict__ x) {
    __shared__ float s_qT[32][36];    // [k][q]
    __shared__ float s_cT[32][132];   // [k][c]
    __shared__ float s_D[32][136];    // [q][c]
    __shared__ float s_sqq[32];
    __shared__ float s_sqc[CT];

    int tid = threadIdx.x, lane = tid & 31;
    int q0 = blockIdx.x * 32;
    int part = blockIdx.y;
    int base0 = part * FPART2;
    int ty = tid >> 4, tx = tid & 15;            // 2 queries x 8 candidates
    int qi = ((tid >> 5) << 2) + (lane >> 3);    // phase-B query (4 per warp)
    int sub = lane & 7;                          // phase-B lane-in-group

    for (int v = tid; v < 1024; v += 256) {
        int k = v & 31, q = v >> 5;
        s_qT[k][q] = x[(size_t)(q0 + q) * INC + k];
    }
    __syncthreads();
    if (tid < 32) {
        float s = 0.f;
#pragma unroll
        for (int k = 0; k < 32; k++) { float v = s_qT[k][tid]; s = fmaf(v, v, s); }
        s_sqq[tid] = s;
    }

    float bd[KNBR]; int bi[KNBR];
#pragma unroll
    for (int r = 0; r < KNBR; r++) { bd[r] = 3.4e38f; bi[r] = 0x7FFFFFFF; }

    for (int tile = 0; tile < FPART2 / CT; tile++) {
        int base = base0 + tile * CT;
        __syncthreads();
        for (int v = tid; v < CT * 32; v += 256) {
            int k = v & 31, c = v >> 5;
            s_cT[k][c] = x[(size_t)(base + c) * INC + k];
        }
        __syncthreads();
        if (tid < CT) {
            float s = 0.f;
#pragma unroll
            for (int k = 0; k < 32; k++) { float v = s_cT[k][tid]; s = fmaf(v, v, s); }
            s_sqc[tid] = s;
        }
        __syncthreads();

        float acc[2][8];
#pragma unroll
        for (int e = 0; e < 2; e++)
#pragma unroll
            for (int j = 0; j < 8; j++) acc[e][j] = 0.f;
#pragma unroll
        for (int k = 0; k < 32; k++) {
            float qv0 = s_qT[k][2 * ty + 0];
            float qv1 = s_qT[k][2 * ty + 1];
            float4 ca = *reinterpret_cast<const float4*>(&s_cT[k][8 * tx]);
            float4 cb = *reinterpret_cast<const float4*>(&s_cT[k][8 * tx + 4]);
            acc[0][0] = fmaf(qv0, ca.x, acc[0][0]); acc[0][1] = fmaf(qv0, ca.y, acc[0][1]);
            acc[0][2] = fmaf(qv0, ca.z, acc[0][2]); acc[0][3] = fmaf(qv0, ca.w, acc[0][3]);
            acc[0][4] = fmaf(qv0, cb.x, acc[0][4]); acc[0][5] = fmaf(qv0, cb.y, acc[0][5]);
            acc[0][6] = fmaf(qv0, cb.z, acc[0][6]); acc[0][7] = fmaf(qv0, cb.w, acc[0][7]);
            acc[1][0] = fmaf(qv1, ca.x, acc[1][0]); acc[1][1] = fmaf(qv1, ca.y, acc[1][1]);
            acc[1][2] = fmaf(qv1, ca.z, acc[1][2]); acc[1][3] = fmaf(qv1, ca.w, acc[1][3]);
            acc[1][4] = fmaf(qv1, cb.x, acc[1][4]); acc[1][5] = fmaf(qv1, cb.y, acc[1][5]);
            acc[1][6] = fmaf(qv1, cb.z, acc[1][6]); acc[1][7] = fmaf(qv1, cb.w, acc[1][7]);
        }
#pragma unroll
        for (int e = 0; e < 2; e++) {
            float sq = s_sqq[2 * ty + e];
            float4 d0 = make_float4((sq + s_sqc[8 * tx + 0]) - 2.0f * acc[e][0],
                                    (sq + s_sqc[8 * tx + 1]) - 2.0f * acc[e][1],
                                    (sq + s_sqc[8 * tx + 2]) - 2.0f * acc[e][2],
                                    (sq + s_sqc[8 * tx + 3]) - 2.0f * acc[e][3]);
            float4 d1 = make_float4((sq + s_sqc[8 * tx + 4]) - 2.0f * acc[e][4],
                                    (sq + s_sqc[8 * tx + 5]) - 2.0f * acc[e][5],
                                    (sq + s_sqc[8 * tx + 6]) - 2.0f * acc[e][6],
                                    (sq + s_sqc[8 * tx + 7]) - 2.0f * acc[e][7]);
            *reinterpret_cast<float4*>(&s_D[2 * ty + e][8 * tx]) = d0;
            *reinterpret_cast<float4*>(&s_D[2 * ty + e][8 * tx + 4]) = d1;
        }
        __syncthreads();

#pragma unroll
        for (int t2 = 0; t2 < CT / 8; t2++) {
            int c = t2 * 8 + sub;
            knn_insert(s_D[qi][c], base + c, bd, bi);
        }
    }
    __syncthreads();

    float* md = reinterpret_cast<float*>(s_cT);
    int*   mi = reinterpret_cast<int*>(s_D);
#pragma unroll
    for (int r = 0; r < KNBR; r++) { md[tid * KNBR + r] = bd[r]; mi[tid * KNBR + r] = bi[r]; }
    __syncwarp();
    int p = 0;
    for (int r = 0; r < KNBR; r++) {
        float cd = (p < KNBR) ? md[tid * KNBR + p] : 3.4e38f;
        int   ci = (p < KNBR) ? mi[tid * KNBR + p] : 0x7FFFFFFF;
        float rd = cd; int ri = ci;
#pragma unroll
        for (int off = 4; off; off >>= 1) {
            float od = __shfl_xor_sync(0xFFFFFFFFu, rd, off);
            int   oi = __shfl_xor_sync(0xFFFFFFFFu, ri, off);
            if (knn_less(od, oi, rd, ri)) { rd = od; ri = oi; }
        }
        if (ci == ri && p < KNBR) p++;
        if (sub == 0) {
            g_pd[1][part][q0 + qi][r] = rd;
            g_pi[1][part][q0 + qi][r] = ri;
        }
    }
}

// ====== fused: buildS (with inline P-way merge) + transposeW side-blocks =======
__global__ __launch_bounds__(128) void buildS_kernel(
    const float* __restrict__ x, const float* __restrict__ pos,
    const float* __restrict__ w1g, const float* __restrict__ b1g,
    const float* __restrict__ w1f, const float* __restrict__ b1f,
    const float* __restrict__ w2g, const float* __restrict__ w2f) {
    int br = blockIdx.y;
    int t = threadIdx.x;

    // ---- transposeW side blocks ----
    if (blockIdx.x >= NND) {
        __shared__ float tile[64][65];
        int kt = blockIdx.x - NND;
        const float* W = br ? w2f : w2g;
        for (int v = t; v < 64 * 64; v += 128) {
            int kk = v >> 6, o = v & 63;
            tile[kk][o] = W[(size_t)(kt * 64 + kk) * 64 + o];
        }
        __syncthreads();
        for (int v = t; v < 64 * 64; v += 128) {
            int o = v >> 6, kk = v & 63;
            float f = tile[kk][o];
            __nv_bfloat16 h = __float2bfloat16(f);
            __nv_bfloat16 l = __float2bfloat16(f - __bfloat162float(h));
            g_Wth[br][(size_t)o * SDIM + kt * 64 + kk] = h;
            g_Wtl[br][(size_t)o * SDIM + kt * 64 + kk] = l;
        }
        return;
    }

    // ---- buildS main blocks ----
    int n = blockIdx.x;
    __shared__ int   s_idx[KNBR];
    __shared__ float s_xj[KNBR][INC];
    __shared__ float s_attr[KNBR][3];
    __shared__ float s_h[KNBR][HID];
    __shared__ float s_pn[3];

    const float* w1 = br ? w1f : w1g;
    const float* b1 = br ? b1f : b1g;

    if (t == 0) {   // exact P-way merge of per-part top-9 lists
        int P = br ? 8 : 2;
        int p[8];
#pragma unroll
        for (int u = 0; u < 8; u++) p[u] = 0;
        for (int r = 0; r < KNBR; r++) {
            float bdv = 3.4e38f; int biv = 0x7FFFFFFF, bt = 0;
            for (int u = 0; u < P; u++) {
                float d = g_pd[br][u][n][p[u]];
                int   i = g_pi[br][u][n][p[u]];
                if (knn_less(d, i, bdv, biv)) { bdv = d; biv = i; bt = u; }
            }
            p[bt]++;
            s_idx[r] = biv;
        }
    }
    if (t < 3) s_pn[t] = pos[n * 3 + t];
    __syncthreads();

    for (int v = t; v < KNBR * INC; v += 128)
        s_xj[v / INC][v % INC] = x[(size_t)s_idx[v / INC] * INC + (v % INC)];

    if (t < KNBR) {
        int sj = s_idx[t];
        float cx = pos[sj * 3 + 0] - s_pn[0];
        float cy = pos[sj * 3 + 1] - s_pn[1];
        float cz = pos[sj * 3 + 2] - s_pn[2];
        float rho = sqrtf((cx * cx + cy * cy) + cz * cz);
        float th  = atan2f(cy, cx);
        float ratio = cz / fmaxf(rho, 1e-12f);
        ratio = fminf(1.0f, fmaxf(-1.0f, ratio));
        float ph = acosf(ratio);
        s_attr[t][0] = rho; s_attr[t][1] = th; s_attr[t][2] = ph;
    }
    __syncthreads();

    {
        int c = t;
        float wa = w1[c], wb = w1[HID + c], wc = w1[2 * HID + c], bb = b1[c];
        float hk[KNBR];
#pragma unroll
        for (int k = 0; k < KNBR; k++)
            hk[k] = tanhf(bb + s_attr[k][0] * wa + s_attr[k][1] * wb + s_attr[k][2] * wc);
#pragma unroll
        for (int k = 0; k < KNBR; k++) s_h[k][c] = hk[k];
    }
    __syncthreads();

    // S: register-blocked xj, packed bf16x2 stores (warp writes 128B contiguous)
    int w = t >> 5, lane = t & 31;
    int i0 = (lane & 15) * 2;
    float xjr0[KNBR], xjr1[KNBR];
#pragma unroll
    for (int k = 0; k < KNBR; k++) { xjr0[k] = s_xj[k][i0]; xjr1[k] = s_xj[k][i0 + 1]; }

    __nv_bfloat162* Sh2 = reinterpret_cast<__nv_bfloat162*>(g_Sh[br] + (size_t)n * SDIM);
    __nv_bfloat162* Sl2 = reinterpret_cast<__nv_bfloat162*>(g_Sl[br] + (size_t)n * SDIM);
#pragma unroll
    for (int j = 0; j < 16; j++) {
        int c = w * 32 + 2 * j + (lane >> 4);
        float s0 = 0.f, s1 = 0.f;
#pragma unroll
        for (int k = 0; k < KNBR; k++) {
            float hv = s_h[k][c];
            s0 = fmaf(hv, xjr0[k], s0);
            s1 = fmaf(hv, xjr1[k], s1);
        }
        __nv_bfloat16 h0 = __float2bfloat16(s0);
        __nv_bfloat16 l0 = __float2bfloat16(s0 - __bfloat162float(h0));
        __nv_bfloat16 h1 = __float2bfloat16(s1);
        __nv_bfloat16 l1 = __float2bfloat16(s1 - __bfloat162float(h1));
        int off2 = c * 16 + (lane & 15);
        __nv_bfloat162 hv2; hv2.x = h0; hv2.y = h1;
        __nv_bfloat162 lv2; lv2.x = l0; lv2.y = l1;
        Sh2[off2] = hv2;
        Sl2[off2] = lv2;
    }
    if (t < INC) {
        float m = 0.f;
#pragma unroll
        for (int k = 0; k < KNBR; k++) m += s_xj[k][t];
        g_xjm[br][n * INC + t] = m * (1.0f / 9.0f);
    }
}

// ================= GEMM via mma.sync bf16 (hi/lo 3-term) + ldmatrix ============
__device__ __forceinline__ void mma_bf16(float* c, const uint32_t* a, const uint32_t* b) {
    asm volatile(
        "mma.sync.aligned.m16n8k16.row.col.f32.bf16.bf16.f32 "
        "{%0,%1,%2,%3}, {%4,%5,%6,%7}, {%8,%9}, {%0,%1,%2,%3};"
        : "+f"(c[0]), "+f"(c[1]), "+f"(c[2]), "+f"(c[3])
        : "r"(a[0]), "r"(a[1]), "r"(a[2]), "r"(a[3]), "r"(b[0]), "r"(b[1]));
}
__device__ __forceinline__ void ldsm_x4(uint32_t& r0, uint32_t& r1, uint32_t& r2,
                                        uint32_t& r3, uint32_t addr) {
    asm volatile("ldmatrix.sync.aligned.m8n8.x4.shared.b16 {%0,%1,%2,%3}, [%4];"
                 : "=r"(r0), "=r"(r1), "=r"(r2), "=r"(r3) : "r"(addr));
}

#define GSMEM_BYTES ((128 * AST * 2 + 64 * AST * 2) * 2)   // 55296 B

__global__ __launch_bounds__(256) void gemm_kernel() {
    extern __shared__ __align__(16) __nv_bfloat16 sm[];
    __nv_bfloat16* Ah = sm;                  // 128 x AST
    __nv_bfloat16* Al = Ah + 128 * AST;
    __nv_bfloat16* Bh = Al + 128 * AST;      // 64 x AST
    __nv_bfloat16* Bl = Bh + 64 * AST;

    int tid = threadIdx.x, warp = tid >> 5, lane = tid & 31;
    int br = blockIdx.y, kz = blockIdx.z;
    int n0 = blockIdx.x * 128;
    int kbase = kz * KLEN;
    int mw = warp >> 1, nw = warp & 1;       // warp tile: m32 x n32
    int g = lane >> 2, t = lane & 3;

    const __nv_bfloat16* ShG = g_Sh[br];
    const __nv_bfloat16* SlG = g_Sl[br];
    const __nv_bfloat16* WhG = g_Wth[br];
    const __nv_bfloat16* WlG = g_Wtl[br];

    uint32_t smemBase = (uint32_t)__cvta_generic_to_shared(sm);
    const uint32_t offAh = 0;
    const uint32_t offAl = 128 * AST * 2;
    const uint32_t offBh = 256 * AST * 2;
    const uint32_t offBl = 256 * AST * 2 + 64 * AST * 2;

    // ldmatrix per-lane row/col mapping (verified against scalar-LDS layout)
    int aRow = (lane & 7) + ((lane >> 3) & 1) * 8;
    int aK   = (lane >> 4) * 8;
    int bRow = ((lane >> 4) * 8) + (lane & 7);
    int bK   = ((lane >> 3) & 1) * 8;

    float acc[2][4][4];
#pragma unroll
    for (int mi = 0; mi < 2; mi++)
#pragma unroll
        for (int ni = 0; ni < 4; ni++)
#pragma unroll
            for (int e = 0; e < 4; e++) acc[mi][ni][e] = 0.f;

    for (int c = 0; c < KLEN / KC; c++) {
        int koff = kbase + c * KC;
        __syncthreads();
#pragma unroll
        for (int u = tid; u < 1024; u += 256) {
            int m = u >> 3, j = u & 7;
            size_t s = (size_t)(n0 + m) * SDIM + koff + j * 8;
            *reinterpret_cast<uint4*>(&Ah[m * AST + j * 8]) =
                *reinterpret_cast<const uint4*>(&ShG[s]);
            *reinterpret_cast<uint4*>(&Al[m * AST + j * 8]) =
                *reinterpret_cast<const uint4*>(&SlG[s]);
        }
#pragma unroll
        for (int u = tid; u < 512; u += 256) {
            int o = u >> 3, j = u & 7;
            size_t s = (size_t)o * SDIM + koff + j * 8;
            *reinterpret_cast<uint4*>(&Bh[o * AST + j * 8]) =
                *reinterpret_cast<const uint4*>(&WhG[s]);
            *reinterpret_cast<uint4*>(&Bl[o * AST + j * 8]) =
                *reinterpret_cast<const uint4*>(&WlG[s]);
        }
        __syncthreads();

#pragma unroll
        for (int ks = 0; ks < KC / 16; ks++) {
            int k0 = ks * 16;
            uint32_t ah[2][4], al[2][4], bh[4][2], bl[4][2];
#pragma unroll
            for (int mi = 0; mi < 2; mi++) {
                uint32_t ao = ((mw * 32 + mi * 16 + aRow) * AST + k0 + aK) * 2;
                ldsm_x4(ah[mi][0], ah[mi][1], ah[mi][2], ah[mi][3], smemBase + offAh + ao);
                ldsm_x4(al[mi][0], al[mi][1], al[mi][2], al[mi][3], smemBase + offAl + ao);
            }
#pragma unroll
            for (int np = 0; np < 2; np++) {
                uint32_t bo = ((nw * 32 + np * 16 + bRow) * AST + k0 + bK) * 2;
                ldsm_x4(bh[2 * np][0], bh[2 * np][1], bh[2 * np + 1][0], bh[2 * np + 1][1],
                        smemBase + offBh + bo);
                ldsm_x4(bl[2 * np][0], bl[2 * np][1], bl[2 * np + 1][0], bl[2 * np + 1][1],
                        smemBase + offBl + bo);
            }
#pragma unroll
            for (int mi = 0; mi < 2; mi++)
#pragma unroll
                for (int ni = 0; ni < 4; ni++) {
                    mma_bf16(acc[mi][ni], ah[mi], bh[ni]);
                    mma_bf16(acc[mi][ni], ah[mi], bl[ni]);
                    mma_bf16(acc[mi][ni], al[mi], bh[ni]);
                }
        }
    }

    float* P = &g_part[br][kz][0][0];
#pragma unroll
    for (int mi = 0; mi < 2; mi++) {
        int r0 = mw * 32 + mi * 16;
#pragma unroll
        for (int ni = 0; ni < 4; ni++) {
            int col = nw * 32 + ni * 8 + 2 * t;
            float2 v01 = make_float2(acc[mi][ni][0], acc[mi][ni][1]);
            float2 v23 = make_float2(acc[mi][ni][2], acc[mi][ni][3]);
            *reinterpret_cast<float2*>(&P[(size_t)(n0 + r0 + g) * OUTC + col]) = v01;
            *reinterpret_cast<float2*>(&P[(size_t)(n0 + r0 + g + 8) * OUTC + col]) = v23;
        }
    }
}

// ================= combine: out = 0.5*((sum parts)/9 + xm@b2 both) =============
__global__ __launch_bounds__(256) void combine_kernel(
    const float* __restrict__ b2g, const float* __restrict__ b2f,
    float* __restrict__ out) {
    __shared__ float s_b2[2][INC * OUTC];
    __shared__ float s_xm[2][4][INC];

    int tid = threadIdx.x;
    int nl = tid >> 6, o = tid & 63;
    int n = blockIdx.x * 4 + nl;

    for (int v = tid; v < INC * OUTC; v += 256) {
        s_b2[0][v] = b2g[v];
        s_b2[1][v] = b2f[v];
    }
    {
        int br = tid >> 7, nn = (tid >> 5) & 3, i = tid & 31;
        s_xm[br][nn][i] = g_xjm[br][(size_t)(blockIdx.x * 4 + nn) * INC + i];
    }
    __syncthreads();

    float val = 0.f;
#pragma unroll
    for (int br = 0; br < 2; br++)
#pragma unroll
        for (int kzi = 0; kzi < KSPL; kzi++)
            val += g_part[br][kzi][n][o];
    val *= (1.0f / 9.0f);
#pragma unroll
    for (int br = 0; br < 2; br++)
#pragma unroll
        for (int i = 0; i < INC; i++)
            val = fmaf(s_xm[br][nl][i], s_b2[br][i * OUTC + o], val);
    out[(size_t)n * OUTC + o] = 0.5f * val;
}

// ---------------- launch -------------------------------------------------------
extern "C" void kernel_launch(void* const* d_in, const int* in_sizes, int n_in,
                              void* d_out, int out_size) {
    const float* x   = (const float*)d_in[0];
    const float* pos = (const float*)d_in[1];
    const float* w1g = (const float*)d_in[2];
    const float* b1g = (const float*)d_in[3];
    const float* w2g = (const float*)d_in[4];
    const float* b2g = (const float*)d_in[5];
    const float* w1f = (const float*)d_in[6];
    const float* b1f = (const float*)d_in[7];
    const float* w2f = (const float*)d_in[8];
    const float* b2f = (const float*)d_in[9];
    float* out = (float*)d_out;

    cudaFuncSetAttribute(gemm_kernel, cudaFuncAttributeMaxDynamicSharedMemorySize,
                         GSMEM_BYTES);

    knn_pos_kernel<<<dim3(NND / 8, 2), 256>>>(pos);                       // 0
    knn_feat_kernel<<<dim3(NND / 32, 8), 256>>>(x);                       // 1
    buildS_kernel<<<dim3(NND + 64, 2), 128>>>(x, pos, w1g, b1g, w1f, b1f,
                                              w2g, w2f);                  // 2
    gemm_kernel<<<dim3(NND / 128, 2, KSPL), 256, GSMEM_BYTES>>>();        // 3 <- profiled
    combine_kernel<<<NND / 4, 256>>>(b2g, b2f, out);                      // 4
}

// round 12
// speedup vs baseline: 1.0819x; 1.0819x over previous
#include <cuda_runtime.h>
#include <cuda_fp16.h>
#include <math.h>
#include <string.h>
#include <stdint.h>

#define NND   4096
#define KNBR  9
#define INC   32
#define OUTC  64
#define HID   128
#define SDIM  4096
#define KSPL  4
#define KLEN  (SDIM / KSPL)   // 1024
#define KC    64
#define AST   72              // smem row stride (halves); 144 B rows
#define MT    64              // gemm node tile

// ---------------- scratch (static device globals; no allocation) ----------------
__device__ float g_pd[2][8][NND][KNBR];
__device__ int   g_pi[2][8][NND][KNBR];
__device__ __half g_Sf[2][(size_t)NND * SDIM];   // fp16 S, 32 MB per branch
__device__ __half g_Wth[2][OUTC * SDIM];         // W^T hi [o][k] fp16
__device__ __half g_Wtl[2][OUTC * SDIM];         // W^T lo [o][k] fp16
__device__ float g_xjm[2][NND * INC];
__device__ float g_part[2][KSPL][NND][OUTC];

// ======================= KNN helpers ===========================================
__device__ __forceinline__ bool knn_less(float d, int i, float d2, int i2) {
    return (d < d2) || (d == d2 && i < i2);
}
__device__ __forceinline__ void knn_insert(float dist, int j, float bd[KNBR], int bi[KNBR]) {
    if (knn_less(dist, j, bd[KNBR - 1], bi[KNBR - 1])) {
        float cd = dist; int ci = j;
#pragma unroll
        for (int r = 0; r < KNBR; r++) {
            bool sw = knn_less(cd, ci, bd[r], bi[r]);
            float td = bd[r]; int ti = bi[r];
            if (sw) { bd[r] = cd; bi[r] = ci; cd = td; ci = ti; }
        }
    }
}
__device__ __forceinline__ void knn_merge_warp(float* md, int* mi, const float bd[KNBR],
                                               const int bi[KNBR], int lane,
                                               float* opd, int* opi, int q) {
#pragma unroll
    for (int r = 0; r < KNBR; r++) { md[lane * KNBR + r] = bd[r]; mi[lane * KNBR + r] = bi[r]; }
    __syncwarp();
    int p = 0;
    for (int r = 0; r < KNBR; r++) {
        float cd = (p < KNBR) ? md[lane * KNBR + p] : 3.4e38f;
        int   ci = (p < KNBR) ? mi[lane * KNBR + p] : 0x7FFFFFFF;
        float rd = cd; int ri = ci;
#pragma unroll
        for (int off = 16; off; off >>= 1) {
            float od = __shfl_xor_sync(0xFFFFFFFFu, rd, off);
            int   oi = __shfl_xor_sync(0xFFFFFFFFu, ri, off);
            if (knn_less(od, oi, rd, ri)) { rd = od; ri = oi; }
        }
        if (ci == ri && p < KNBR) p++;
        if (lane == 0) { opd[q * KNBR + r] = rd; opi[q * KNBR + r] = ri; }
    }
    __syncwarp();
}

// ---------------- fused KNN: blocks [0,1024) = feat, [1024,2048) = pos ---------
#define CT 128
#define FPART2 (NND / 8)
#define PPART  (NND / 2)

struct FeatS {
    float qT[32][36];
    float cT[32][132];
    float D[32][136];
    float sqq[32];
    float sqc[CT];
};

__global__ __launch_bounds__(256) void knn_kernel(const float* __restrict__ x,
                                                  const float* __restrict__ pos) {
    __shared__ __align__(16) char smbuf[sizeof(FeatS)];
    int tid = threadIdx.x, lane = tid & 31;
    int id = blockIdx.x;

    if (id < 1024) {
        // ======================= feat branch =======================
        FeatS* fs = reinterpret_cast<FeatS*>(smbuf);
        int bx = id >> 3, part = id & 7;
        int q0 = bx * 32;
        int base0 = part * FPART2;
        int ty = tid >> 4, tx = tid & 15;
        int qi = ((tid >> 5) << 2) + (lane >> 3);
        int sub = lane & 7;

        for (int v = tid; v < 1024; v += 256) {
            int k = v & 31, q = v >> 5;
            fs->qT[k][q] = x[(size_t)(q0 + q) * INC + k];
        }
        __syncthreads();
        if (tid < 32) {
            float s = 0.f;
#pragma unroll
            for (int k = 0; k < 32; k++) { float v = fs->qT[k][tid]; s = fmaf(v, v, s); }
            fs->sqq[tid] = s;
        }

        float bd[KNBR]; int bi[KNBR];
#pragma unroll
        for (int r = 0; r < KNBR; r++) { bd[r] = 3.4e38f; bi[r] = 0x7FFFFFFF; }

        for (int tile = 0; tile < FPART2 / CT; tile++) {
            int base = base0 + tile * CT;
            __syncthreads();
            for (int v = tid; v < CT * 32; v += 256) {
                int k = v & 31, c = v >> 5;
                fs->cT[k][c] = x[(size_t)(base + c) * INC + k];
            }
            __syncthreads();
            if (tid < CT) {
                float s = 0.f;
#pragma unroll
                for (int k = 0; k < 32; k++) { float v = fs->cT[k][tid]; s = fmaf(v, v, s); }
                fs->sqc[tid] = s;
            }
            __syncthreads();

            float acc[2][8];
#pragma unroll
            for (int e = 0; e < 2; e++)
#pragma unroll
                for (int j = 0; j < 8; j++) acc[e][j] = 0.f;
#pragma unroll
            for (int k = 0; k < 32; k++) {
                float qv0 = fs->qT[k][2 * ty + 0];
                float qv1 = fs->qT[k][2 * ty + 1];
                float4 ca = *reinterpret_cast<const float4*>(&fs->cT[k][8 * tx]);
                float4 cb = *reinterpret_cast<const float4*>(&fs->cT[k][8 * tx + 4]);
                acc[0][0] = fmaf(qv0, ca.x, acc[0][0]); acc[0][1] = fmaf(qv0, ca.y, acc[0][1]);
                acc[0][2] = fmaf(qv0, ca.z, acc[0][2]); acc[0][3] = fmaf(qv0, ca.w, acc[0][3]);
                acc[0][4] = fmaf(qv0, cb.x, acc[0][4]); acc[0][5] = fmaf(qv0, cb.y, acc[0][5]);
                acc[0][6] = fmaf(qv0, cb.z, acc[0][6]); acc[0][7] = fmaf(qv0, cb.w, acc[0][7]);
                acc[1][0] = fmaf(qv1, ca.x, acc[1][0]); acc[1][1] = fmaf(qv1, ca.y, acc[1][1]);
                acc[1][2] = fmaf(qv1, ca.z, acc[1][2]); acc[1][3] = fmaf(qv1, ca.w, acc[1][3]);
                acc[1][4] = fmaf(qv1, cb.x, acc[1][4]); acc[1][5] = fmaf(qv1, cb.y, acc[1][5]);
                acc[1][6] = fmaf(qv1, cb.z, acc[1][6]); acc[1][7] = fmaf(qv1, cb.w, acc[1][7]);
            }
#pragma unroll
            for (int e = 0; e < 2; e++) {
                float sq = fs->sqq[2 * ty + e];
                float4 d0 = make_float4((sq + fs->sqc[8 * tx + 0]) - 2.0f * acc[e][0],
                                        (sq + fs->sqc[8 * tx + 1]) - 2.0f * acc[e][1],
                                        (sq + fs->sqc[8 * tx + 2]) - 2.0f * acc[e][2],
                                        (sq + fs->sqc[8 * tx + 3]) - 2.0f * acc[e][3]);
                float4 d1 = make_float4((sq + fs->sqc[8 * tx + 4]) - 2.0f * acc[e][4],
                                        (sq + fs->sqc[8 * tx + 5]) - 2.0f * acc[e][5],
                                        (sq + fs->sqc[8 * tx + 6]) - 2.0f * acc[e][6],
                                        (sq + fs->sqc[8 * tx + 7]) - 2.0f * acc[e][7]);
                *reinterpret_cast<float4*>(&fs->D[2 * ty + e][8 * tx]) = d0;
                *reinterpret_cast<float4*>(&fs->D[2 * ty + e][8 * tx + 4]) = d1;
            }
            __syncthreads();

#pragma unroll
            for (int t2 = 0; t2 < CT / 8; t2++) {
                int c = t2 * 8 + sub;
                knn_insert(fs->D[qi][c], base + c, bd, bi);
            }
        }
        __syncthreads();

        float* md = &fs->cT[0][0];
        int*   mi = reinterpret_cast<int*>(&fs->D[0][0]);
#pragma unroll
        for (int r = 0; r < KNBR; r++) { md[tid * KNBR + r] = bd[r]; mi[tid * KNBR + r] = bi[r]; }
        __syncwarp();
        int p = 0;
        for (int r = 0; r < KNBR; r++) {
            float cd = (p < KNBR) ? md[tid * KNBR + p] : 3.4e38f;
            int   ci = (p < KNBR) ? mi[tid * KNBR + p] : 0x7FFFFFFF;
            float rd = cd; int ri = ci;
#pragma unroll
            for (int off = 4; off; off >>= 1) {
                float od = __shfl_xor_sync(0xFFFFFFFFu, rd, off);
                int   oi = __shfl_xor_sync(0xFFFFFFFFu, ri, off);
                if (knn_less(od, oi, rd, ri)) { rd = od; ri = oi; }
            }
            if (ci == ri && p < KNBR) p++;
            if (sub == 0) {
                g_pd[1][part][q0 + qi][r] = rd;
                g_pi[1][part][q0 + qi][r] = ri;
            }
        }
    } else {
        // ======================= pos branch =======================
        float* psm = reinterpret_cast<float*>(smbuf);
        int id2 = id - 1024;
        int bx = id2 & 511, part = id2 >> 9;
        int w = tid >> 5;
        int q = bx * 8 + w;
        int base = part * PPART;

        for (int v = tid; v < PPART * 3; v += 256) psm[v] = pos[base * 3 + v];
        __syncthreads();

        float q0 = pos[q * 3 + 0], q1 = pos[q * 3 + 1], q2 = pos[q * 3 + 2];
        float sqq = 0.f;
        sqq = fmaf(q0, q0, sqq); sqq = fmaf(q1, q1, sqq); sqq = fmaf(q2, q2, sqq);

        float bd[KNBR]; int bi[KNBR];
#pragma unroll
        for (int r = 0; r < KNBR; r++) { bd[r] = 3.4e38f; bi[r] = 0x7FFFFFFF; }

        for (int jl = lane; jl < PPART; jl += 128) {
            float dist[4];
#pragma unroll
            for (int u = 0; u < 4; u++) {
                int jj = jl + u * 32;
                float c0 = psm[jj * 3 + 0], c1 = psm[jj * 3 + 1], c2 = psm[jj * 3 + 2];
                float acc = 0.f;
                acc = fmaf(q0, c0, acc); acc = fmaf(q1, c1, acc); acc = fmaf(q2, c2, acc);
                float sqj = 0.f;
                sqj = fmaf(c0, c0, sqj); sqj = fmaf(c1, c1, sqj); sqj = fmaf(c2, c2, sqj);
                dist[u] = (sqq + sqj) - 2.0f * acc;
            }
#pragma unroll
            for (int u = 0; u < 4; u++) knn_insert(dist[u], base + jl + u * 32, bd, bi);
        }
        __syncthreads();

        float* md = psm + (size_t)w * 288;
        int*   mi = (int*)(psm + 8 * 288) + (size_t)w * 288;
        knn_merge_warp(md, mi, bd, bi, lane, &g_pd[0][part][0][0], &g_pi[0][part][0][0], q);
    }
}

// ====== buildS (inline P-way merge) + transposeW side-blocks, per branch =======
__global__ __launch_bounds__(128) void buildS_kernel(
    const float* __restrict__ x, const float* __restrict__ pos,
    const float* __restrict__ w1, const float* __restrict__ b1,
    const float* __restrict__ w2, int br) {
    int t = threadIdx.x;

    // ---- transposeW side blocks ----
    if (blockIdx.x >= NND) {
        __shared__ float tile[64][65];
        int kt = blockIdx.x - NND;
        for (int v = t; v < 64 * 64; v += 128) {
            int kk = v >> 6, o = v & 63;
            tile[kk][o] = w2[(size_t)(kt * 64 + kk) * 64 + o];
        }
        __syncthreads();
        for (int v = t; v < 64 * 64; v += 128) {
            int o = v >> 6, kk = v & 63;
            float f = tile[kk][o];
            __half h = __float2half_rn(f);
            __half l = __float2half_rn(f - __half2float(h));
            g_Wth[br][(size_t)o * SDIM + kt * 64 + kk] = h;
            g_Wtl[br][(size_t)o * SDIM + kt * 64 + kk] = l;
        }
        return;
    }

    // ---- buildS main blocks ----
    int n = blockIdx.x;
    __shared__ int   s_idx[KNBR];
    __shared__ float s_xj[KNBR][INC];
    __shared__ float s_attr[KNBR][3];
    __shared__ float s_h[KNBR][HID];
    __shared__ float s_pn[3];

    if (t == 0) {   // exact P-way merge of per-part top-9 lists
        int P = br ? 8 : 2;
        int p[8];
#pragma unroll
        for (int u = 0; u < 8; u++) p[u] = 0;
        for (int r = 0; r < KNBR; r++) {
            float bdv = 3.4e38f; int biv = 0x7FFFFFFF, bt = 0;
            for (int u = 0; u < P; u++) {
                float d = g_pd[br][u][n][p[u]];
                int   i = g_pi[br][u][n][p[u]];
                if (knn_less(d, i, bdv, biv)) { bdv = d; biv = i; bt = u; }
            }
            p[bt]++;
            s_idx[r] = biv;
        }
    }
    if (t < 3) s_pn[t] = pos[n * 3 + t];
    __syncthreads();

    for (int v = t; v < KNBR * INC; v += 128)
        s_xj[v / INC][v % INC] = x[(size_t)s_idx[v / INC] * INC + (v % INC)];

    if (t < KNBR) {
        int sj = s_idx[t];
        float cx = pos[sj * 3 + 0] - s_pn[0];
        float cy = pos[sj * 3 + 1] - s_pn[1];
        float cz = pos[sj * 3 + 2] - s_pn[2];
        float rho = sqrtf((cx * cx + cy * cy) + cz * cz);
        float th  = atan2f(cy, cx);
        float ratio = cz / fmaxf(rho, 1e-12f);
        ratio = fminf(1.0f, fmaxf(-1.0f, ratio));
        float ph = acosf(ratio);
        s_attr[t][0] = rho; s_attr[t][1] = th; s_attr[t][2] = ph;
    }
    __syncthreads();

    {
        int c = t;
        float wa = w1[c], wb = w1[HID + c], wc = w1[2 * HID + c], bb = b1[c];
        float hk[KNBR];
#pragma unroll
        for (int k = 0; k < KNBR; k++)
            hk[k] = tanhf(bb + s_attr[k][0] * wa + s_attr[k][1] * wb + s_attr[k][2] * wc);
#pragma unroll
        for (int k = 0; k < KNBR; k++) s_h[k][c] = hk[k];
    }
    __syncthreads();

    // S: register-blocked xj, packed fp16x2 stores
    int w = t >> 5, lane = t & 31;
    int i0 = (lane & 15) * 2;
    float xjr0[KNBR], xjr1[KNBR];
#pragma unroll
    for (int k = 0; k < KNBR; k++) { xjr0[k] = s_xj[k][i0]; xjr1[k] = s_xj[k][i0 + 1]; }

    __half2* Sf2 = reinterpret_cast<__half2*>(g_Sf[br] + (size_t)n * SDIM);
#pragma unroll
    for (int j = 0; j < 16; j++) {
        int c = w * 32 + 2 * j + (lane >> 4);
        float s0 = 0.f, s1 = 0.f;
#pragma unroll
        for (int k = 0; k < KNBR; k++) {
            float hv = s_h[k][c];
            s0 = fmaf(hv, xjr0[k], s0);
            s1 = fmaf(hv, xjr1[k], s1);
        }
        Sf2[c * 16 + (lane & 15)] = __halves2half2(__float2half_rn(s0), __float2half_rn(s1));
    }
    if (t < INC) {
        float m = 0.f;
#pragma unroll
        for (int k = 0; k < KNBR; k++) m += s_xj[k][t];
        g_xjm[br][n * INC + t] = m * (1.0f / 9.0f);
    }
}

// ================= GEMM via mma.sync f16 (S single + W hi/lo) + ldmatrix =======
__device__ __forceinline__ void mma_f16(float* c, const uint32_t* a, const uint32_t* b) {
    asm volatile(
        "mma.sync.aligned.m16n8k16.row.col.f32.f16.f16.f32 "
        "{%0,%1,%2,%3}, {%4,%5,%6,%7}, {%8,%9}, {%0,%1,%2,%3};"
        : "+f"(c[0]), "+f"(c[1]), "+f"(c[2]), "+f"(c[3])
        : "r"(a[0]), "r"(a[1]), "r"(a[2]), "r"(a[3]), "r"(b[0]), "r"(b[1]));
}
__device__ __forceinline__ void ldsm_x4(uint32_t& r0, uint32_t& r1, uint32_t& r2,
                                        uint32_t& r3, uint32_t addr) {
    asm volatile("ldmatrix.sync.aligned.m8n8.x4.shared.b16 {%0,%1,%2,%3}, [%4];"
                 : "=r"(r0), "=r"(r1), "=r"(r2), "=r"(r3) : "r"(addr));
}

__global__ __launch_bounds__(256, 3) void gemm_kernel() {
    __shared__ __align__(16) __half Af[MT * AST];    // 9.2 KB
    __shared__ __align__(16) __half Bh_[64 * AST];   // 9.2 KB
    __shared__ __align__(16) __half Bl_[64 * AST];   // 9.2 KB

    int tid = threadIdx.x, warp = tid >> 5, lane = tid & 31;
    int br = blockIdx.y, kz = blockIdx.z;
    int n0 = blockIdx.x * MT;
    int kbase = kz * KLEN;
    int mw = warp & 1, nw = warp >> 1;       // warp tile: m32 x n16
    int g = lane >> 2, t = lane & 3;

    const uint4* SfP = reinterpret_cast<const uint4*>(g_Sf[br]);
    const uint4* WhP = reinterpret_cast<const uint4*>(g_Wth[br]);
    const uint4* WlP = reinterpret_cast<const uint4*>(g_Wtl[br]);

    uint32_t aBase  = (uint32_t)__cvta_generic_to_shared(Af);
    uint32_t bhBase = (uint32_t)__cvta_generic_to_shared(Bh_);
    uint32_t blBase = (uint32_t)__cvta_generic_to_shared(Bl_);

    int aRow = (lane & 7) + ((lane >> 3) & 1) * 8;
    int aK   = (lane >> 4) * 8;
    int bRow = ((lane >> 4) * 8) + (lane & 7);
    int bK   = ((lane >> 3) & 1) * 8;

    float acc[2][2][4];
#pragma unroll
    for (int mi = 0; mi < 2; mi++)
#pragma unroll
        for (int ni = 0; ni < 2; ni++)
#pragma unroll
            for (int e = 0; e < 4; e++) acc[mi][ni][e] = 0.f;

    for (int c = 0; c < KLEN / KC; c++) {
        int koff = kbase + c * KC;
        __syncthreads();
        // stage A: MT rows x 8 16B-units (512 units)
#pragma unroll
        for (int u = tid; u < MT * 8; u += 256) {
            int m = u >> 3, j = u & 7;
            size_t s = ((size_t)(n0 + m) * SDIM + koff) / 8 + j;
            *reinterpret_cast<uint4*>(&Af[m * AST + j * 8]) = SfP[s];
        }
        // stage B hi/lo: 64 rows x 8 units each
#pragma unroll
        for (int u = tid; u < 512; u += 256) {
            int o = u >> 3, j = u & 7;
            size_t s = ((size_t)o * SDIM + koff) / 8 + j;
            *reinterpret_cast<uint4*>(&Bh_[o * AST + j * 8]) = WhP[s];
            *reinterpret_cast<uint4*>(&Bl_[o * AST + j * 8]) = WlP[s];
        }
        __syncthreads();

#pragma unroll
        for (int ks = 0; ks < KC / 16; ks++) {
            int k0 = ks * 16;
            uint32_t ah[2][4], bh[2][2], bl[2][2];
#pragma unroll
            for (int mi = 0; mi < 2; mi++) {
                uint32_t ao = ((mw * 32 + mi * 16 + aRow) * AST + k0 + aK) * 2;
                ldsm_x4(ah[mi][0], ah[mi][1], ah[mi][2], ah[mi][3], aBase + ao);
            }
            {
                uint32_t bo = ((nw * 16 + bRow) * AST + k0 + bK) * 2;
                ldsm_x4(bh[0][0], bh[0][1], bh[1][0], bh[1][1], bhBase + bo);
                ldsm_x4(bl[0][0], bl[0][1], bl[1][0], bl[1][1], blBase + bo);
            }
#pragma unroll
            for (int mi = 0; mi < 2; mi++)
#pragma unroll
                for (int ni = 0; ni < 2; ni++) {
                    mma_f16(acc[mi][ni], ah[mi], bh[ni]);
                    mma_f16(acc[mi][ni], ah[mi], bl[ni]);
                }
        }
    }

    float* P = &g_part[br][kz][0][0];
#pragma unroll
    for (int mi = 0; mi < 2; mi++) {
        int r0 = n0 + mw * 32 + mi * 16;
#pragma unroll
        for (int ni = 0; ni < 2; ni++) {
            int col = nw * 16 + ni * 8 + 2 * t;
            float2 v01 = make_float2(acc[mi][ni][0], acc[mi][ni][1]);
            float2 v23 = make_float2(acc[mi][ni][2], acc[mi][ni][3]);
            *reinterpret_cast<float2*>(&P[(size_t)(r0 + g) * OUTC + col]) = v01;
            *reinterpret_cast<float2*>(&P[(size_t)(r0 + g + 8) * OUTC + col]) = v23;
        }
    }
}

// ================= combine: out = 0.5*((sum parts)/9 + xm@b2 both) =============
__global__ __launch_bounds__(256) void combine_kernel(
    const float* __restrict__ b2g, const float* __restrict__ b2f,
    float* __restrict__ out) {
    __shared__ float s_b2[2][INC * OUTC];
    __shared__ float s_xm[2][4][INC];

    int tid = threadIdx.x;
    int nl = tid >> 6, o = tid & 63;
    int n = blockIdx.x * 4 + nl;

    for (int v = tid; v < INC * OUTC; v += 256) {
        s_b2[0][v] = b2g[v];
        s_b2[1][v] = b2f[v];
    }
    {
        int br = tid >> 7, nn = (tid >> 5) & 3, i = tid & 31;
        s_xm[br][nn][i] = g_xjm[br][(size_t)(blockIdx.x * 4 + nn) * INC + i];
    }
    __syncthreads();

    float val = 0.f;
#pragma unroll
    for (int br = 0; br < 2; br++)
#pragma unroll
        for (int kzi = 0; kzi < KSPL; kzi++)
            val += g_part[br][kzi][n][o];
    val *= (1.0f / 9.0f);
#pragma unroll
    for (int br = 0; br < 2; br++)
#pragma unroll
        for (int i = 0; i < INC; i++)
            val = fmaf(s_xm[br][nl][i], s_b2[br][i * OUTC + o], val);
    out[(size_t)n * OUTC + o] = 0.5f * val;
}

// ---------------- launch -------------------------------------------------------
extern "C" void kernel_launch(void* const* d_in, const int* in_sizes, int n_in,
                              void* d_out, int out_size) {
    const float* x   = (const float*)d_in[0];
    const float* pos = (const float*)d_in[1];
    const float* w1g = (const float*)d_in[2];
    const float* b1g = (const float*)d_in[3];
    const float* w2g = (const float*)d_in[4];
    const float* b2g = (const float*)d_in[5];
    const float* w1f = (const float*)d_in[6];
    const float* b1f = (const float*)d_in[7];
    const float* w2f = (const float*)d_in[8];
    const float* b2f = (const float*)d_in[9];
    float* out = (float*)d_out;

    knn_kernel<<<2048, 256>>>(x, pos);                                    // 0
    buildS_kernel<<<NND + 64, 128>>>(x, pos, w1g, b1g, w2g, 0);           // 1
    buildS_kernel<<<NND + 64, 128>>>(x, pos, w1f, b1f, w2f, 1);           // 2
    gemm_kernel<<<dim3(NND / MT, 2, KSPL), 256>>>();                      // 3 <- profiled
    combine_kernel<<<NND / 4, 256>>>(b2g, b2f, out);                      // 4
}

// round 13
// speedup vs baseline: 1.1200x; 1.0353x over previous
#include <cuda_runtime.h>
#include <cuda_fp16.h>
#include <math.h>
#include <string.h>
#include <stdint.h>

#define NND   4096
#define KNBR  9
#define INC   32
#define OUTC  64
#define HID   128
#define SDIM  4096
#define KSPL  4
#define KLEN  (SDIM / KSPL)   // 1024
#define KC    64
#define AST   72              // smem row stride (halves); 144 B rows
#define MT    64              // gemm node tile

// ---------------- scratch (static device globals; no allocation) ----------------
__device__ float g_pd[2][8][NND][KNBR];
__device__ int   g_pi[2][8][NND][KNBR];
__device__ __half g_Sf[2][(size_t)NND * SDIM];   // fp16 S, 32 MB per branch
__device__ __half g_Wth[2][OUTC * SDIM];         // W^T hi [o][k] fp16
__device__ __half g_Wtl[2][OUTC * SDIM];         // W^T lo [o][k] fp16
__device__ float g_xjm[2][NND * INC];
__device__ float g_part[2][KSPL][NND][OUTC];

// ======================= KNN helpers ===========================================
__device__ __forceinline__ bool knn_less(float d, int i, float d2, int i2) {
    return (d < d2) || (d == d2 && i < i2);
}
__device__ __forceinline__ void knn_insert(float dist, int j, float bd[KNBR], int bi[KNBR]) {
    if (knn_less(dist, j, bd[KNBR - 1], bi[KNBR - 1])) {
        float cd = dist; int ci = j;
#pragma unroll
        for (int r = 0; r < KNBR; r++) {
            bool sw = knn_less(cd, ci, bd[r], bi[r]);
            float td = bd[r]; int ti = bi[r];
            if (sw) { bd[r] = cd; bi[r] = ci; cd = td; ci = ti; }
        }
    }
}
__device__ __forceinline__ void knn_merge_warp(float* md, int* mi, const float bd[KNBR],
                                               const int bi[KNBR], int lane,
                                               float* opd, int* opi, int q) {
#pragma unroll
    for (int r = 0; r < KNBR; r++) { md[lane * KNBR + r] = bd[r]; mi[lane * KNBR + r] = bi[r]; }
    __syncwarp();
    int p = 0;
    for (int r = 0; r < KNBR; r++) {
        float cd = (p < KNBR) ? md[lane * KNBR + p] : 3.4e38f;
        int   ci = (p < KNBR) ? mi[lane * KNBR + p] : 0x7FFFFFFF;
        float rd = cd; int ri = ci;
#pragma unroll
        for (int off = 16; off; off >>= 1) {
            float od = __shfl_xor_sync(0xFFFFFFFFu, rd, off);
            int   oi = __shfl_xor_sync(0xFFFFFFFFu, ri, off);
            if (knn_less(od, oi, rd, ri)) { rd = od; ri = oi; }
        }
        if (ci == ri && p < KNBR) p++;
        if (lane == 0) { opd[q * KNBR + r] = rd; opi[q * KNBR + r] = ri; }
    }
    __syncwarp();
}

// ---------------- fused KNN: blocks [0,1024) = feat, [1024,2048) = pos ---------
#define CT 128
#define FPART2 (NND / 8)
#define PPART  (NND / 2)

// feat smem: qT + big (cT / D / merge aliased) + norms = 23.7 KB; pos needs 24.6 KB
struct FeatS {
    float qT[32][36];     // 4608 B
    float big[4608];      // 18432 B: cT (stride 132) / D (stride 136) / merge buffers
    float sqq[32];
    float sqc[CT];
};
#define SMBUF_BYTES 24704

__global__ __launch_bounds__(256) void knn_kernel(const float* __restrict__ x,
                                                  const float* __restrict__ pos) {
    __shared__ __align__(16) char smbuf[SMBUF_BYTES];
    int tid = threadIdx.x, lane = tid & 31;
    int id = blockIdx.x;

    if (id < 1024) {
        // ======================= feat branch =======================
        FeatS* fs = reinterpret_cast<FeatS*>(smbuf);
        float* cT = fs->big;                 // [k][c] stride 132, alive in phase A only
        float* D  = fs->big;                 // [q][c] stride 136, alive in phase B only
        int bx = id >> 3, part = id & 7;
        int q0 = bx * 32;
        int base0 = part * FPART2;
        int ty = tid >> 4, tx = tid & 15;
        int qi = ((tid >> 5) << 2) + (lane >> 3);
        int sub = lane & 7;

        for (int v = tid; v < 1024; v += 256) {
            int k = v & 31, q = v >> 5;
            fs->qT[k][q] = x[(size_t)(q0 + q) * INC + k];
        }
        __syncthreads();
        if (tid < 32) {
            float s = 0.f;
#pragma unroll
            for (int k = 0; k < 32; k++) { float v = fs->qT[k][tid]; s = fmaf(v, v, s); }
            fs->sqq[tid] = s;
        }

        float bd[KNBR]; int bi[KNBR];
#pragma unroll
        for (int r = 0; r < KNBR; r++) { bd[r] = 3.4e38f; bi[r] = 0x7FFFFFFF; }

        for (int tile = 0; tile < FPART2 / CT; tile++) {
            int base = base0 + tile * CT;
            __syncthreads();   // phase B of prev tile done -> safe to restage cT
            for (int v = tid; v < CT * 32; v += 256) {
                int k = v & 31, c = v >> 5;
                cT[k * 132 + c] = x[(size_t)(base + c) * INC + k];
            }
            __syncthreads();
            if (tid < CT) {
                float s = 0.f;
#pragma unroll
                for (int k = 0; k < 32; k++) { float v = cT[k * 132 + tid]; s = fmaf(v, v, s); }
                fs->sqc[tid] = s;
            }
            __syncthreads();

            float acc[2][8];
#pragma unroll
            for (int e = 0; e < 2; e++)
#pragma unroll
                for (int j = 0; j < 8; j++) acc[e][j] = 0.f;
#pragma unroll
            for (int k = 0; k < 32; k++) {
                float qv0 = fs->qT[k][2 * ty + 0];
                float qv1 = fs->qT[k][2 * ty + 1];
                float4 ca = *reinterpret_cast<const float4*>(&cT[k * 132 + 8 * tx]);
                float4 cb = *reinterpret_cast<const float4*>(&cT[k * 132 + 8 * tx + 4]);
                acc[0][0] = fmaf(qv0, ca.x, acc[0][0]); acc[0][1] = fmaf(qv0, ca.y, acc[0][1]);
                acc[0][2] = fmaf(qv0, ca.z, acc[0][2]); acc[0][3] = fmaf(qv0, ca.w, acc[0][3]);
                acc[0][4] = fmaf(qv0, cb.x, acc[0][4]); acc[0][5] = fmaf(qv0, cb.y, acc[0][5]);
                acc[0][6] = fmaf(qv0, cb.z, acc[0][6]); acc[0][7] = fmaf(qv0, cb.w, acc[0][7]);
                acc[1][0] = fmaf(qv1, ca.x, acc[1][0]); acc[1][1] = fmaf(qv1, ca.y, acc[1][1]);
                acc[1][2] = fmaf(qv1, ca.z, acc[1][2]); acc[1][3] = fmaf(qv1, ca.w, acc[1][3]);
                acc[1][4] = fmaf(qv1, cb.x, acc[1][4]); acc[1][5] = fmaf(qv1, cb.y, acc[1][5]);
                acc[1][6] = fmaf(qv1, cb.z, acc[1][6]); acc[1][7] = fmaf(qv1, cb.w, acc[1][7]);
            }
            __syncthreads();   // cT reads done -> safe to overwrite with D
#pragma unroll
            for (int e = 0; e < 2; e++) {
                float sq = fs->sqq[2 * ty + e];
                float4 d0 = make_float4((sq + fs->sqc[8 * tx + 0]) - 2.0f * acc[e][0],
                                        (sq + fs->sqc[8 * tx + 1]) - 2.0f * acc[e][1],
                                        (sq + fs->sqc[8 * tx + 2]) - 2.0f * acc[e][2],
                                        (sq + fs->sqc[8 * tx + 3]) - 2.0f * acc[e][3]);
                float4 d1 = make_float4((sq + fs->sqc[8 * tx + 4]) - 2.0f * acc[e][4],
                                        (sq + fs->sqc[8 * tx + 5]) - 2.0f * acc[e][5],
                                        (sq + fs->sqc[8 * tx + 6]) - 2.0f * acc[e][6],
                                        (sq + fs->sqc[8 * tx + 7]) - 2.0f * acc[e][7]);
                *reinterpret_cast<float4*>(&D[(2 * ty + e) * 136 + 8 * tx]) = d0;
                *reinterpret_cast<float4*>(&D[(2 * ty + e) * 136 + 8 * tx + 4]) = d1;
            }
            __syncthreads();

#pragma unroll
            for (int t2 = 0; t2 < CT / 8; t2++) {
                int c = t2 * 8 + sub;
                knn_insert(D[qi * 136 + c], base + c, bd, bi);
            }
        }
        __syncthreads();   // phase B done; overlay merge buffers on big

        float* md = fs->big;
        int*   mi = reinterpret_cast<int*>(fs->big + 2304);
#pragma unroll
        for (int r = 0; r < KNBR; r++) { md[tid * KNBR + r] = bd[r]; mi[tid * KNBR + r] = bi[r]; }
        __syncwarp();
        int p = 0;
        for (int r = 0; r < KNBR; r++) {
            float cd = (p < KNBR) ? md[tid * KNBR + p] : 3.4e38f;
            int   ci = (p < KNBR) ? mi[tid * KNBR + p] : 0x7FFFFFFF;
            float rd = cd; int ri = ci;
#pragma unroll
            for (int off = 4; off; off >>= 1) {
                float od = __shfl_xor_sync(0xFFFFFFFFu, rd, off);
                int   oi = __shfl_xor_sync(0xFFFFFFFFu, ri, off);
                if (knn_less(od, oi, rd, ri)) { rd = od; ri = oi; }
            }
            if (ci == ri && p < KNBR) p++;
            if (sub == 0) {
                g_pd[1][part][q0 + qi][r] = rd;
                g_pi[1][part][q0 + qi][r] = ri;
            }
        }
    } else {
        // ======================= pos branch =======================
        float* psm = reinterpret_cast<float*>(smbuf);
        int id2 = id - 1024;
        int bx = id2 & 511, part = id2 >> 9;
        int w = tid >> 5;
        int q = bx * 8 + w;
        int base = part * PPART;

        for (int v = tid; v < PPART * 3; v += 256) psm[v] = pos[base * 3 + v];
        __syncthreads();

        float q0 = pos[q * 3 + 0], q1 = pos[q * 3 + 1], q2 = pos[q * 3 + 2];
        float sqq = 0.f;
        sqq = fmaf(q0, q0, sqq); sqq = fmaf(q1, q1, sqq); sqq = fmaf(q2, q2, sqq);

        float bd[KNBR]; int bi[KNBR];
#pragma unroll
        for (int r = 0; r < KNBR; r++) { bd[r] = 3.4e38f; bi[r] = 0x7FFFFFFF; }

        for (int jl = lane; jl < PPART; jl += 128) {
            float dist[4];
#pragma unroll
            for (int u = 0; u < 4; u++) {
                int jj = jl + u * 32;
                float c0 = psm[jj * 3 + 0], c1 = psm[jj * 3 + 1], c2 = psm[jj * 3 + 2];
                float acc = 0.f;
                acc = fmaf(q0, c0, acc); acc = fmaf(q1, c1, acc); acc = fmaf(q2, c2, acc);
                float sqj = 0.f;
                sqj = fmaf(c0, c0, sqj); sqj = fmaf(c1, c1, sqj); sqj = fmaf(c2, c2, sqj);
                dist[u] = (sqq + sqj) - 2.0f * acc;
            }
#pragma unroll
            for (int u = 0; u < 4; u++) knn_insert(dist[u], base + jl + u * 32, bd, bi);
        }
        __syncthreads();

        float* md = psm + (size_t)w * 288;
        int*   mi = (int*)(psm + 8 * 288) + (size_t)w * 288;
        knn_merge_warp(md, mi, bd, bi, lane, &g_pd[0][part][0][0], &g_pi[0][part][0][0], q);
    }
}

// ====== buildS (inline P-way merge) + transposeW side-blocks, per branch =======
__global__ __launch_bounds__(128) void buildS_kernel(
    const float* __restrict__ x, const float* __restrict__ pos,
    const float* __restrict__ w1, const float* __restrict__ b1,
    const float* __restrict__ w2, int br) {
    int t = threadIdx.x;

    if (blockIdx.x >= NND) {
        __shared__ float tile[64][65];
        int kt = blockIdx.x - NND;
        for (int v = t; v < 64 * 64; v += 128) {
            int kk = v >> 6, o = v & 63;
            tile[kk][o] = w2[(size_t)(kt * 64 + kk) * 64 + o];
        }
        __syncthreads();
        for (int v = t; v < 64 * 64; v += 128) {
            int o = v >> 6, kk = v & 63;
            float f = tile[kk][o];
            __half h = __float2half_rn(f);
            __half l = __float2half_rn(f - __half2float(h));
            g_Wth[br][(size_t)o * SDIM + kt * 64 + kk] = h;
            g_Wtl[br][(size_t)o * SDIM + kt * 64 + kk] = l;
        }
        return;
    }

    int n = blockIdx.x;
    __shared__ int   s_idx[KNBR];
    __shared__ float s_xj[KNBR][INC];
    __shared__ float s_attr[KNBR][3];
    __shared__ float s_h[KNBR][HID];
    __shared__ float s_pn[3];

    if (t == 0) {
        int P = br ? 8 : 2;
        int p[8];
#pragma unroll
        for (int u = 0; u < 8; u++) p[u] = 0;
        for (int r = 0; r < KNBR; r++) {
            float bdv = 3.4e38f; int biv = 0x7FFFFFFF, bt = 0;
            for (int u = 0; u < P; u++) {
                float d = g_pd[br][u][n][p[u]];
                int   i = g_pi[br][u][n][p[u]];
                if (knn_less(d, i, bdv, biv)) { bdv = d; biv = i; bt = u; }
            }
            p[bt]++;
            s_idx[r] = biv;
        }
    }
    if (t < 3) s_pn[t] = pos[n * 3 + t];
    __syncthreads();

    for (int v = t; v < KNBR * INC; v += 128)
        s_xj[v / INC][v % INC] = x[(size_t)s_idx[v / INC] * INC + (v % INC)];

    if (t < KNBR) {
        int sj = s_idx[t];
        float cx = pos[sj * 3 + 0] - s_pn[0];
        float cy = pos[sj * 3 + 1] - s_pn[1];
        float cz = pos[sj * 3 + 2] - s_pn[2];
        float rho = sqrtf((cx * cx + cy * cy) + cz * cz);
        float th  = atan2f(cy, cx);
        float ratio = cz / fmaxf(rho, 1e-12f);
        ratio = fminf(1.0f, fmaxf(-1.0f, ratio));
        float ph = acosf(ratio);
        s_attr[t][0] = rho; s_attr[t][1] = th; s_attr[t][2] = ph;
    }
    __syncthreads();

    {
        int c = t;
        float wa = w1[c], wb = w1[HID + c], wc = w1[2 * HID + c], bb = b1[c];
        float hk[KNBR];
#pragma unroll
        for (int k = 0; k < KNBR; k++)
            hk[k] = tanhf(bb + s_attr[k][0] * wa + s_attr[k][1] * wb + s_attr[k][2] * wc);
#pragma unroll
        for (int k = 0; k < KNBR; k++) s_h[k][c] = hk[k];
    }
    __syncthreads();

    int w = t >> 5, lane = t & 31;
    int i0 = (lane & 15) * 2;
    float xjr0[KNBR], xjr1[KNBR];
#pragma unroll
    for (int k = 0; k < KNBR; k++) { xjr0[k] = s_xj[k][i0]; xjr1[k] = s_xj[k][i0 + 1]; }

    __half2* Sf2 = reinterpret_cast<__half2*>(g_Sf[br] + (size_t)n * SDIM);
#pragma unroll
    for (int j = 0; j < 16; j++) {
        int c = w * 32 + 2 * j + (lane >> 4);
        float s0 = 0.f, s1 = 0.f;
#pragma unroll
        for (int k = 0; k < KNBR; k++) {
            float hv = s_h[k][c];
            s0 = fmaf(hv, xjr0[k], s0);
            s1 = fmaf(hv, xjr1[k], s1);
        }
        Sf2[c * 16 + (lane & 15)] = __halves2half2(__float2half_rn(s0), __float2half_rn(s1));
    }
    if (t < INC) {
        float m = 0.f;
#pragma unroll
        for (int k = 0; k < KNBR; k++) m += s_xj[k][t];
        g_xjm[br][n * INC + t] = m * (1.0f / 9.0f);
    }
}

// ================= GEMM: cp.async double-buffered, mma f16 + ldmatrix ==========
__device__ __forceinline__ void mma_f16(float* c, const uint32_t* a, const uint32_t* b) {
    asm volatile(
        "mma.sync.aligned.m16n8k16.row.col.f32.f16.f16.f32 "
        "{%0,%1,%2,%3}, {%4,%5,%6,%7}, {%8,%9}, {%0,%1,%2,%3};"
        : "+f"(c[0]), "+f"(c[1]), "+f"(c[2]), "+f"(c[3])
        : "r"(a[0]), "r"(a[1]), "r"(a[2]), "r"(a[3]), "r"(b[0]), "r"(b[1]));
}
__device__ __forceinline__ void ldsm_x4(uint32_t& r0, uint32_t& r1, uint32_t& r2,
                                        uint32_t& r3, uint32_t addr) {
    asm volatile("ldmatrix.sync.aligned.m8n8.x4.shared.b16 {%0,%1,%2,%3}, [%4];"
                 : "=r"(r0), "=r"(r1), "=r"(r2), "=r"(r3) : "r"(addr));
}
__device__ __forceinline__ void cp16(uint32_t dst, const void* src) {
    asm volatile("cp.async.ca.shared.global [%0], [%1], 16;" :: "r"(dst), "l"(src));
}
#define CP_COMMIT() asm volatile("cp.async.commit_group;" ::: "memory")
#define CP_WAIT1()  asm volatile("cp.async.wait_group 1;" ::: "memory")
#define CP_WAIT0()  asm volatile("cp.async.wait_group 0;" ::: "memory")

#define STAGE_BYTES (3 * 64 * AST * 2)   // A + Bh + Bl per stage = 27648 B
#define GSMEM_BYTES (2 * STAGE_BYTES)    // 55296 B

__global__ __launch_bounds__(256, 2) void gemm_kernel() {
    extern __shared__ __align__(16) __half sm[];

    int tid = threadIdx.x, warp = tid >> 5, lane = tid & 31;
    int br = blockIdx.y, kz = blockIdx.z;
    int n0 = blockIdx.x * MT;
    int kbase = kz * KLEN;
    int mw = warp & 1, nw = warp >> 1;       // warp tile: m32 x n16
    int g = lane >> 2, t = lane & 3;

    const __half* SfG = g_Sf[br];
    const __half* WhG = g_Wth[br];
    const __half* WlG = g_Wtl[br];

    uint32_t smBase = (uint32_t)__cvta_generic_to_shared(sm);
    // per-stage offsets: A=0, Bh=9216, Bl=18432

    // staging map: A 512 units (2/thread), B 512 units (2/thread, hi+lo each)
    int am = tid >> 3, aj = tid & 7;          // unit tid: m=am, j=aj (first half)
    int bo_ = tid >> 3, bj = tid & 7;

    // issue one stage of cp.asyncs
    auto issue_stage = [&](int st, int koff) {
        uint32_t base = smBase + st * STAGE_BYTES;
#pragma unroll
        for (int h = 0; h < 2; h++) {
            int m = am + h * 32;
            cp16(base + (m * AST + aj * 8) * 2,
                 SfG + (size_t)(n0 + m) * SDIM + koff + aj * 8);
        }
#pragma unroll
        for (int h = 0; h < 2; h++) {
            int o = bo_ + h * 32;
            size_t src = (size_t)o * SDIM + koff + bj * 8;
            cp16(base + 9216 + (o * AST + bj * 8) * 2, WhG + src);
            cp16(base + 18432 + (o * AST + bj * 8) * 2, WlG + src);
        }
        CP_COMMIT();
    };

    int aRow = (lane & 7) + ((lane >> 3) & 1) * 8;
    int aK   = (lane >> 4) * 8;
    int bRow = ((lane >> 4) * 8) + (lane & 7);
    int bK   = ((lane >> 3) & 1) * 8;

    float acc[2][2][4];
#pragma unroll
    for (int mi = 0; mi < 2; mi++)
#pragma unroll
        for (int ni = 0; ni < 2; ni++)
#pragma unroll
            for (int e = 0; e < 4; e++) acc[mi][ni][e] = 0.f;

    const int NCH = KLEN / KC;   // 16
    issue_stage(0, kbase);

    for (int c = 0; c < NCH; c++) {
        int st = c & 1;
        __syncthreads();   // prior compute on buffer (c+1)&1 finished
        if (c + 1 < NCH) issue_stage((c + 1) & 1, kbase + (c + 1) * KC);
        if (c + 1 < NCH) { CP_WAIT1(); } else { CP_WAIT0(); }
        __syncthreads();

        uint32_t base = smBase + st * STAGE_BYTES;
#pragma unroll
        for (int ks = 0; ks < KC / 16; ks++) {
            int k0 = ks * 16;
            uint32_t ah[2][4], bh[2][2], bl[2][2];
#pragma unroll
            for (int mi = 0; mi < 2; mi++) {
                uint32_t ao = ((mw * 32 + mi * 16 + aRow) * AST + k0 + aK) * 2;
                ldsm_x4(ah[mi][0], ah[mi][1], ah[mi][2], ah[mi][3], base + ao);
            }
            {
                uint32_t bo = ((nw * 16 + bRow) * AST + k0 + bK) * 2;
                ldsm_x4(bh[0][0], bh[0][1], bh[1][0], bh[1][1], base + 9216 + bo);
                ldsm_x4(bl[0][0], bl[0][1], bl[1][0], bl[1][1], base + 18432 + bo);
            }
#pragma unroll
            for (int mi = 0; mi < 2; mi++)
#pragma unroll
                for (int ni = 0; ni < 2; ni++) {
                    mma_f16(acc[mi][ni], ah[mi], bh[ni]);
                    mma_f16(acc[mi][ni], ah[mi], bl[ni]);
                }
        }
    }

    float* P = &g_part[br][kz][0][0];
#pragma unroll
    for (int mi = 0; mi < 2; mi++) {
        int r0 = n0 + mw * 32 + mi * 16;
#pragma unroll
        for (int ni = 0; ni < 2; ni++) {
            int col = nw * 16 + ni * 8 + 2 * t;
            float2 v01 = make_float2(acc[mi][ni][0], acc[mi][ni][1]);
            float2 v23 = make_float2(acc[mi][ni][2], acc[mi][ni][3]);
            *reinterpret_cast<float2*>(&P[(size_t)(r0 + g) * OUTC + col]) = v01;
            *reinterpret_cast<float2*>(&P[(size_t)(r0 + g + 8) * OUTC + col]) = v23;
        }
    }
}

// ================= combine: out = 0.5*((sum parts)/9 + xm@b2 both) =============
__global__ __launch_bounds__(256) void combine_kernel(
    const float* __restrict__ b2g, const float* __restrict__ b2f,
    float* __restrict__ out) {
    __shared__ float s_b2[2][INC * OUTC];
    __shared__ float s_xm[2][4][INC];

    int tid = threadIdx.x;
    int nl = tid >> 6, o = tid & 63;
    int n = blockIdx.x * 4 + nl;

    for (int v = tid; v < INC * OUTC; v += 256) {
        s_b2[0][v] = b2g[v];
        s_b2[1][v] = b2f[v];
    }
    {
        int br = tid >> 7, nn = (tid >> 5) & 3, i = tid & 31;
        s_xm[br][nn][i] = g_xjm[br][(size_t)(blockIdx.x * 4 + nn) * INC + i];
    }
    __syncthreads();

    float val = 0.f;
#pragma unroll
    for (int br = 0; br < 2; br++)
#pragma unroll
        for (int kzi = 0; kzi < KSPL; kzi++)
            val += g_part[br][kzi][n][o];
    val *= (1.0f / 9.0f);
#pragma unroll
    for (int br = 0; br < 2; br++)
#pragma unroll
        for (int i = 0; i < INC; i++)
            val = fmaf(s_xm[br][nl][i], s_b2[br][i * OUTC + o], val);
    out[(size_t)n * OUTC + o] = 0.5f * val;
}

// ---------------- launch -------------------------------------------------------
extern "C" void kernel_launch(void* const* d_in, const int* in_sizes, int n_in,
                              void* d_out, int out_size) {
    const float* x   = (const float*)d_in[0];
    const float* pos = (const float*)d_in[1];
    const float* w1g = (const float*)d_in[2];
    const float* b1g = (const float*)d_in[3];
    const float* w2g = (const float*)d_in[4];
    const float* b2g = (const float*)d_in[5];
    const float* w1f = (const float*)d_in[6];
    const float* b1f = (const float*)d_in[7];
    const float* w2f = (const float*)d_in[8];
    const float* b2f = (const float*)d_in[9];
    float* out = (float*)d_out;

    cudaFuncSetAttribute(gemm_kernel, cudaFuncAttributeMaxDynamicSharedMemorySize,
                         GSMEM_BYTES);

    knn_kernel<<<2048, 256>>>(x, pos);                                    // 0
    buildS_kernel<<<NND + 64, 128>>>(x, pos, w1g, b1g, w2g, 0);           // 1
    buildS_kernel<<<NND + 64, 128>>>(x, pos, w1f, b1f, w2f, 1);           // 2
    gemm_kernel<<<dim3(NND / MT, 2, KSPL), 256, GSMEM_BYTES>>>();         // 3 <- profiled
    combine_kernel<<<NND / 4, 256>>>(b2g, b2f, out);                      // 4
}

// round 14
// speedup vs baseline: 1.2092x; 1.0796x over previous
#include <cuda_runtime.h>
#include <cuda_fp16.h>
#include <math.h>
#include <string.h>
#include <stdint.h>

#define NND   4096
#define KNBR  9
#define INC   32
#define OUTC  64
#define HID   128
#define SDIM  4096
#define KSPL  4
#define KLEN  (SDIM / KSPL)   // 1024
#define KC    64
#define AST   72              // smem row stride (halves); 144 B rows
#define MT    64              // gemm node tile

// ---------------- scratch (static device globals; no allocation) ----------------
__device__ float g_pd[2][8][NND][KNBR];
__device__ int   g_pi[2][8][NND][KNBR];
__device__ __half g_Sf[2][(size_t)NND * SDIM];   // fp16 S, 32 MB per branch
__device__ __half g_Wt[2][OUTC * SDIM];          // W^T [o][k] fp16
__device__ float g_xjm[2][NND * INC];
__device__ float g_part[2][KSPL][NND][OUTC];

// ======================= KNN helpers ===========================================
__device__ __forceinline__ bool knn_less(float d, int i, float d2, int i2) {
    return (d < d2) || (d == d2 && i < i2);
}
__device__ __forceinline__ void knn_insert(float dist, int j, float bd[KNBR], int bi[KNBR]) {
    if (knn_less(dist, j, bd[KNBR - 1], bi[KNBR - 1])) {
        float cd = dist; int ci = j;
#pragma unroll
        for (int r = 0; r < KNBR; r++) {
            bool sw = knn_less(cd, ci, bd[r], bi[r]);
            float td = bd[r]; int ti = bi[r];
            if (sw) { bd[r] = cd; bi[r] = ci; cd = td; ci = ti; }
        }
    }
}
__device__ __forceinline__ void knn_merge_warp(float* md, int* mi, const float bd[KNBR],
                                               const int bi[KNBR], int lane,
                                               float* opd, int* opi, int q) {
#pragma unroll
    for (int r = 0; r < KNBR; r++) { md[lane * KNBR + r] = bd[r]; mi[lane * KNBR + r] = bi[r]; }
    __syncwarp();
    int p = 0;
    for (int r = 0; r < KNBR; r++) {
        float cd = (p < KNBR) ? md[lane * KNBR + p] : 3.4e38f;
        int   ci = (p < KNBR) ? mi[lane * KNBR + p] : 0x7FFFFFFF;
        float rd = cd; int ri = ci;
#pragma unroll
        for (int off = 16; off; off >>= 1) {
            float od = __shfl_xor_sync(0xFFFFFFFFu, rd, off);
            int   oi = __shfl_xor_sync(0xFFFFFFFFu, ri, off);
            if (knn_less(od, oi, rd, ri)) { rd = od; ri = oi; }
        }
        if (ci == ri && p < KNBR) p++;
        if (lane == 0) { opd[q * KNBR + r] = rd; opi[q * KNBR + r] = ri; }
    }
    __syncwarp();
}

// ------- fused KNN: blocks [0,512) = feat (4 parts), [512,1536) = pos ----------
#define CT 128
#define FPARTS 4
#define FPART2 (NND / FPARTS)   // 1024
#define PPART  (NND / 2)

struct FeatS {
    float qT[32][36];     // 4608 B
    float big[4608];      // 18432 B: cT (stride 132) / D (stride 136) / merge buffers
    float sqq[32];
    float sqc[CT];
};
#define SMBUF_BYTES 24704

__global__ __launch_bounds__(256) void knn_kernel(const float* __restrict__ x,
                                                  const float* __restrict__ pos) {
    __shared__ __align__(16) char smbuf[SMBUF_BYTES];
    int tid = threadIdx.x, lane = tid & 31;
    int id = blockIdx.x;

    if (id < 512) {
        // ======================= feat branch =======================
        FeatS* fs = reinterpret_cast<FeatS*>(smbuf);
        float* cT = fs->big;
        float* D  = fs->big;
        int bx = id >> 2, part = id & 3;
        int q0 = bx * 32;
        int base0 = part * FPART2;
        int ty = tid >> 4, tx = tid & 15;
        int qi = ((tid >> 5) << 2) + (lane >> 3);
        int sub = lane & 7;

        for (int v = tid; v < 1024; v += 256) {
            int k = v & 31, q = v >> 5;
            fs->qT[k][q] = x[(size_t)(q0 + q) * INC + k];
        }
        __syncthreads();
        if (tid < 32) {
            float s = 0.f;
#pragma unroll
            for (int k = 0; k < 32; k++) { float v = fs->qT[k][tid]; s = fmaf(v, v, s); }
            fs->sqq[tid] = s;
        }

        float bd[KNBR]; int bi[KNBR];
#pragma unroll
        for (int r = 0; r < KNBR; r++) { bd[r] = 3.4e38f; bi[r] = 0x7FFFFFFF; }

        for (int tile = 0; tile < FPART2 / CT; tile++) {
            int base = base0 + tile * CT;
            __syncthreads();
            for (int v = tid; v < CT * 32; v += 256) {
                int k = v & 31, c = v >> 5;
                cT[k * 132 + c] = x[(size_t)(base + c) * INC + k];
            }
            __syncthreads();
            if (tid < CT) {
                float s = 0.f;
#pragma unroll
                for (int k = 0; k < 32; k++) { float v = cT[k * 132 + tid]; s = fmaf(v, v, s); }
                fs->sqc[tid] = s;
            }
            __syncthreads();

            float acc[2][8];
#pragma unroll
            for (int e = 0; e < 2; e++)
#pragma unroll
                for (int j = 0; j < 8; j++) acc[e][j] = 0.f;
#pragma unroll
            for (int k = 0; k < 32; k++) {
                float qv0 = fs->qT[k][2 * ty + 0];
                float qv1 = fs->qT[k][2 * ty + 1];
                float4 ca = *reinterpret_cast<const float4*>(&cT[k * 132 + 8 * tx]);
                float4 cb = *reinterpret_cast<const float4*>(&cT[k * 132 + 8 * tx + 4]);
                acc[0][0] = fmaf(qv0, ca.x, acc[0][0]); acc[0][1] = fmaf(qv0, ca.y, acc[0][1]);
                acc[0][2] = fmaf(qv0, ca.z, acc[0][2]); acc[0][3] = fmaf(qv0, ca.w, acc[0][3]);
                acc[0][4] = fmaf(qv0, cb.x, acc[0][4]); acc[0][5] = fmaf(qv0, cb.y, acc[0][5]);
                acc[0][6] = fmaf(qv0, cb.z, acc[0][6]); acc[0][7] = fmaf(qv0, cb.w, acc[0][7]);
                acc[1][0] = fmaf(qv1, ca.x, acc[1][0]); acc[1][1] = fmaf(qv1, ca.y, acc[1][1]);
                acc[1][2] = fmaf(qv1, ca.z, acc[1][2]); acc[1][3] = fmaf(qv1, ca.w, acc[1][3]);
                acc[1][4] = fmaf(qv1, cb.x, acc[1][4]); acc[1][5] = fmaf(qv1, cb.y, acc[1][5]);
                acc[1][6] = fmaf(qv1, cb.z, acc[1][6]); acc[1][7] = fmaf(qv1, cb.w, acc[1][7]);
            }
            __syncthreads();
#pragma unroll
            for (int e = 0; e < 2; e++) {
                float sq = fs->sqq[2 * ty + e];
                float4 d0 = make_float4((sq + fs->sqc[8 * tx + 0]) - 2.0f * acc[e][0],
                                        (sq + fs->sqc[8 * tx + 1]) - 2.0f * acc[e][1],
                                        (sq + fs->sqc[8 * tx + 2]) - 2.0f * acc[e][2],
                                        (sq + fs->sqc[8 * tx + 3]) - 2.0f * acc[e][3]);
                float4 d1 = make_float4((sq + fs->sqc[8 * tx + 4]) - 2.0f * acc[e][4],
                                        (sq + fs->sqc[8 * tx + 5]) - 2.0f * acc[e][5],
                                        (sq + fs->sqc[8 * tx + 6]) - 2.0f * acc[e][6],
                                        (sq + fs->sqc[8 * tx + 7]) - 2.0f * acc[e][7]);
                *reinterpret_cast<float4*>(&D[(2 * ty + e) * 136 + 8 * tx]) = d0;
                *reinterpret_cast<float4*>(&D[(2 * ty + e) * 136 + 8 * tx + 4]) = d1;
            }
            __syncthreads();

#pragma unroll
            for (int t2 = 0; t2 < CT / 8; t2++) {
                int c = t2 * 8 + sub;
                knn_insert(D[qi * 136 + c], base + c, bd, bi);
            }
        }
        __syncthreads();

        float* md = fs->big;
        int*   mi = reinterpret_cast<int*>(fs->big + 2304);
#pragma unroll
        for (int r = 0; r < KNBR; r++) { md[tid * KNBR + r] = bd[r]; mi[tid * KNBR + r] = bi[r]; }
        __syncwarp();
        int p = 0;
        for (int r = 0; r < KNBR; r++) {
            float cd = (p < KNBR) ? md[tid * KNBR + p] : 3.4e38f;
            int   ci = (p < KNBR) ? mi[tid * KNBR + p] : 0x7FFFFFFF;
            float rd = cd; int ri = ci;
#pragma unroll
            for (int off = 4; off; off >>= 1) {
                float od = __shfl_xor_sync(0xFFFFFFFFu, rd, off);
                int   oi = __shfl_xor_sync(0xFFFFFFFFu, ri, off);
                if (knn_less(od, oi, rd, ri)) { rd = od; ri = oi; }
            }
            if (ci == ri && p < KNBR) p++;
            if (sub == 0) {
                g_pd[1][part][q0 + qi][r] = rd;
                g_pi[1][part][q0 + qi][r] = ri;
            }
        }
    } else {
        // ======================= pos branch =======================
        float* psm = reinterpret_cast<float*>(smbuf);
        int id2 = id - 512;
        int bx = id2 & 511, part = id2 >> 9;
        int w = tid >> 5;
        int q = bx * 8 + w;
        int base = part * PPART;

        for (int v = tid; v < PPART * 3; v += 256) psm[v] = pos[base * 3 + v];
        __syncthreads();

        float q0 = pos[q * 3 + 0], q1 = pos[q * 3 + 1], q2 = pos[q * 3 + 2];
        float sqq = 0.f;
        sqq = fmaf(q0, q0, sqq); sqq = fmaf(q1, q1, sqq); sqq = fmaf(q2, q2, sqq);

        float bd[KNBR]; int bi[KNBR];
#pragma unroll
        for (int r = 0; r < KNBR; r++) { bd[r] = 3.4e38f; bi[r] = 0x7FFFFFFF; }

        for (int jl = lane; jl < PPART; jl += 128) {
            float dist[4];
#pragma unroll
            for (int u = 0; u < 4; u++) {
                int jj = jl + u * 32;
                float c0 = psm[jj * 3 + 0], c1 = psm[jj * 3 + 1], c2 = psm[jj * 3 + 2];
                float acc = 0.f;
                acc = fmaf(q0, c0, acc); acc = fmaf(q1, c1, acc); acc = fmaf(q2, c2, acc);
                float sqj = 0.f;
                sqj = fmaf(c0, c0, sqj); sqj = fmaf(c1, c1, sqj); sqj = fmaf(c2, c2, sqj);
                dist[u] = (sqq + sqj) - 2.0f * acc;
            }
#pragma unroll
            for (int u = 0; u < 4; u++) knn_insert(dist[u], base + jl + u * 32, bd, bi);
        }
        __syncthreads();

        float* md = psm + (size_t)w * 288;
        int*   mi = (int*)(psm + 8 * 288) + (size_t)w * 288;
        knn_merge_warp(md, mi, bd, bi, lane, &g_pd[0][part][0][0], &g_pi[0][part][0][0], q);
    }
}

// ====== buildS (inline P-way merge) + transposeW side-blocks, per branch =======
__global__ __launch_bounds__(128) void buildS_kernel(
    const float* __restrict__ x, const float* __restrict__ pos,
    const float* __restrict__ w1, const float* __restrict__ b1,
    const float* __restrict__ w2, int br) {
    int t = threadIdx.x;

    if (blockIdx.x >= NND) {
        __shared__ float tile[64][65];
        int kt = blockIdx.x - NND;
        for (int v = t; v < 64 * 64; v += 128) {
            int kk = v >> 6, o = v & 63;
            tile[kk][o] = w2[(size_t)(kt * 64 + kk) * 64 + o];
        }
        __syncthreads();
        for (int v = t; v < 64 * 64; v += 128) {
            int o = v >> 6, kk = v & 63;
            g_Wt[br][(size_t)o * SDIM + kt * 64 + kk] = __float2half_rn(tile[kk][o]);
        }
        return;
    }

    int n = blockIdx.x;
    __shared__ int   s_idx[KNBR];
    __shared__ float s_xj[KNBR][INC];
    __shared__ float s_attr[KNBR][3];
    __shared__ float s_h[KNBR][HID];
    __shared__ float s_pn[3];

    if (t == 0) {
        int P = br ? FPARTS : 2;
        int p[8];
#pragma unroll
        for (int u = 0; u < 8; u++) p[u] = 0;
        for (int r = 0; r < KNBR; r++) {
            float bdv = 3.4e38f; int biv = 0x7FFFFFFF, bt = 0;
            for (int u = 0; u < P; u++) {
                float d = g_pd[br][u][n][p[u]];
                int   i = g_pi[br][u][n][p[u]];
                if (knn_less(d, i, bdv, biv)) { bdv = d; biv = i; bt = u; }
            }
            p[bt]++;
            s_idx[r] = biv;
        }
    }
    if (t < 3) s_pn[t] = pos[n * 3 + t];
    __syncthreads();

    for (int v = t; v < KNBR * INC; v += 128)
        s_xj[v / INC][v % INC] = x[(size_t)s_idx[v / INC] * INC + (v % INC)];

    if (t < KNBR) {
        int sj = s_idx[t];
        float cx = pos[sj * 3 + 0] - s_pn[0];
        float cy = pos[sj * 3 + 1] - s_pn[1];
        float cz = pos[sj * 3 + 2] - s_pn[2];
        float rho = sqrtf((cx * cx + cy * cy) + cz * cz);
        float th  = atan2f(cy, cx);
        float ratio = cz / fmaxf(rho, 1e-12f);
        ratio = fminf(1.0f, fmaxf(-1.0f, ratio));
        float ph = acosf(ratio);
        s_attr[t][0] = rho; s_attr[t][1] = th; s_attr[t][2] = ph;
    }
    __syncthreads();

    {
        int c = t;
        float wa = w1[c], wb = w1[HID + c], wc = w1[2 * HID + c], bb = b1[c];
        float hk[KNBR];
#pragma unroll
        for (int k = 0; k < KNBR; k++)
            hk[k] = tanhf(bb + s_attr[k][0] * wa + s_attr[k][1] * wb + s_attr[k][2] * wc);
#pragma unroll
        for (int k = 0; k < KNBR; k++) s_h[k][c] = hk[k];
    }
    __syncthreads();

    int w = t >> 5, lane = t & 31;
    int i0 = (lane & 15) * 2;
    float xjr0[KNBR], xjr1[KNBR];
#pragma unroll
    for (int k = 0; k < KNBR; k++) { xjr0[k] = s_xj[k][i0]; xjr1[k] = s_xj[k][i0 + 1]; }

    __half2* Sf2 = reinterpret_cast<__half2*>(g_Sf[br] + (size_t)n * SDIM);
#pragma unroll
    for (int j = 0; j < 16; j++) {
        int c = w * 32 + 2 * j + (lane >> 4);
        float s0 = 0.f, s1 = 0.f;
#pragma unroll
        for (int k = 0; k < KNBR; k++) {
            float hv = s_h[k][c];
            s0 = fmaf(hv, xjr0[k], s0);
            s1 = fmaf(hv, xjr1[k], s1);
        }
        Sf2[c * 16 + (lane & 15)] = __halves2half2(__float2half_rn(s0), __float2half_rn(s1));
    }
    if (t < INC) {
        float m = 0.f;
#pragma unroll
        for (int k = 0; k < KNBR; k++) m += s_xj[k][t];
        g_xjm[br][n * INC + t] = m * (1.0f / 9.0f);
    }
}

// ================= GEMM: cp.async double-buffered, mma f16 (single W) ==========
__device__ __forceinline__ void mma_f16(float* c, const uint32_t* a, const uint32_t* b) {
    asm volatile(
        "mma.sync.aligned.m16n8k16.row.col.f32.f16.f16.f32 "
        "{%0,%1,%2,%3}, {%4,%5,%6,%7}, {%8,%9}, {%0,%1,%2,%3};"
        : "+f"(c[0]), "+f"(c[1]), "+f"(c[2]), "+f"(c[3])
        : "r"(a[0]), "r"(a[1]), "r"(a[2]), "r"(a[3]), "r"(b[0]), "r"(b[1]));
}
__device__ __forceinline__ void ldsm_x4(uint32_t& r0, uint32_t& r1, uint32_t& r2,
                                        uint32_t& r3, uint32_t addr) {
    asm volatile("ldmatrix.sync.aligned.m8n8.x4.shared.b16 {%0,%1,%2,%3}, [%4];"
                 : "=r"(r0), "=r"(r1), "=r"(r2), "=r"(r3) : "r"(addr));
}
__device__ __forceinline__ void cp16(uint32_t dst, const void* src) {
    asm volatile("cp.async.ca.shared.global [%0], [%1], 16;" :: "r"(dst), "l"(src));
}
#define CP_COMMIT() asm volatile("cp.async.commit_group;" ::: "memory")
#define CP_WAIT1()  asm volatile("cp.async.wait_group 1;" ::: "memory")
#define CP_WAIT0()  asm volatile("cp.async.wait_group 0;" ::: "memory")

#define STAGE_BYTES (2 * 64 * AST * 2)   // A + B per stage = 18432 B
#define GSMEM_BYTES (2 * STAGE_BYTES)    // 36864 B

__global__ __launch_bounds__(256, 4) void gemm_kernel() {
    extern __shared__ __align__(16) __half sm[];

    int tid = threadIdx.x, warp = tid >> 5, lane = tid & 31;
    int br = blockIdx.y, kz = blockIdx.z;
    int n0 = blockIdx.x * MT;
    int kbase = kz * KLEN;
    int mw = warp & 1, nw = warp >> 1;       // warp tile: m32 x n16
    int g = lane >> 2, t = lane & 3;

    const __half* SfG = g_Sf[br];
    const __half* WG  = g_Wt[br];

    uint32_t smBase = (uint32_t)__cvta_generic_to_shared(sm);
    // per-stage: A at 0, B at 9216

    int am = tid >> 3, aj = tid & 7;

    auto issue_stage = [&](int st, int koff) {
        uint32_t base = smBase + st * STAGE_BYTES;
#pragma unroll
        for (int h = 0; h < 2; h++) {
            int m = am + h * 32;
            cp16(base + (m * AST + aj * 8) * 2,
                 SfG + (size_t)(n0 + m) * SDIM + koff + aj * 8);
        }
#pragma unroll
        for (int h = 0; h < 2; h++) {
            int o = am + h * 32;
            cp16(base + 9216 + (o * AST + aj * 8) * 2,
                 WG + (size_t)o * SDIM + koff + aj * 8);
        }
        CP_COMMIT();
    };

    int aRow = (lane & 7) + ((lane >> 3) & 1) * 8;
    int aK   = (lane >> 4) * 8;
    int bRow = ((lane >> 4) * 8) + (lane & 7);
    int bK   = ((lane >> 3) & 1) * 8;

    float acc[2][2][4];
#pragma unroll
    for (int mi = 0; mi < 2; mi++)
#pragma unroll
        for (int ni = 0; ni < 2; ni++)
#pragma unroll
            for (int e = 0; e < 4; e++) acc[mi][ni][e] = 0.f;

    const int NCH = KLEN / KC;   // 16
    issue_stage(0, kbase);

    for (int c = 0; c < NCH; c++) {
        int st = c & 1;
        __syncthreads();
        if (c + 1 < NCH) issue_stage((c + 1) & 1, kbase + (c + 1) * KC);
        if (c + 1 < NCH) { CP_WAIT1(); } else { CP_WAIT0(); }
        __syncthreads();

        uint32_t base = smBase + st * STAGE_BYTES;
#pragma unroll
        for (int ks = 0; ks < KC / 16; ks++) {
            int k0 = ks * 16;
            uint32_t ah[2][4], bh[2][2];
#pragma unroll
            for (int mi = 0; mi < 2; mi++) {
                uint32_t ao = ((mw * 32 + mi * 16 + aRow) * AST + k0 + aK) * 2;
                ldsm_x4(ah[mi][0], ah[mi][1], ah[mi][2], ah[mi][3], base + ao);
            }
            {
                uint32_t bo = ((nw * 16 + bRow) * AST + k0 + bK) * 2;
                ldsm_x4(bh[0][0], bh[0][1], bh[1][0], bh[1][1], base + 9216 + bo);
            }
#pragma unroll
            for (int mi = 0; mi < 2; mi++)
#pragma unroll
                for (int ni = 0; ni < 2; ni++)
                    mma_f16(acc[mi][ni], ah[mi], bh[ni]);
        }
    }

    float* P = &g_part[br][kz][0][0];
#pragma unroll
    for (int mi = 0; mi < 2; mi++) {
        int r0 = n0 + mw * 32 + mi * 16;
#pragma unroll
        for (int ni = 0; ni < 2; ni++) {
            int col = nw * 16 + ni * 8 + 2 * t;
            float2 v01 = make_float2(acc[mi][ni][0], acc[mi][ni][1]);
            float2 v23 = make_float2(acc[mi][ni][2], acc[mi][ni][3]);
            *reinterpret_cast<float2*>(&P[(size_t)(r0 + g) * OUTC + col]) = v01;
            *reinterpret_cast<float2*>(&P[(size_t)(r0 + g + 8) * OUTC + col]) = v23;
        }
    }
}

// ================= combine: out = 0.5*((sum parts)/9 + xm@b2 both) =============
__global__ __launch_bounds__(256) void combine_kernel(
    const float* __restrict__ b2g, const float* __restrict__ b2f,
    float* __restrict__ out) {
    __shared__ float s_b2[2][INC * OUTC];
    __shared__ float s_xm[2][4][INC];

    int tid = threadIdx.x;
    int nl = tid >> 6, o = tid & 63;
    int n = blockIdx.x * 4 + nl;

    for (int v = tid; v < INC * OUTC; v += 256) {
        s_b2[0][v] = b2g[v];
        s_b2[1][v] = b2f[v];
    }
    {
        int br = tid >> 7, nn = (tid >> 5) & 3, i = tid & 31;
        s_xm[br][nn][i] = g_xjm[br][(size_t)(blockIdx.x * 4 + nn) * INC + i];
    }
    __syncthreads();

    float val = 0.f;
#pragma unroll
    for (int br = 0; br < 2; br++)
#pragma unroll
        for (int kzi = 0; kzi < KSPL; kzi++)
            val += g_part[br][kzi][n][o];
    val *= (1.0f / 9.0f);
#pragma unroll
    for (int br = 0; br < 2; br++)
#pragma unroll
        for (int i = 0; i < INC; i++)
            val = fmaf(s_xm[br][nl][i], s_b2[br][i * OUTC + o], val);
    out[(size_t)n * OUTC + o] = 0.5f * val;
}

// ---------------- launch -------------------------------------------------------
extern "C" void kernel_launch(void* const* d_in, const int* in_sizes, int n_in,
                              void* d_out, int out_size) {
    const float* x   = (const float*)d_in[0];
    const float* pos = (const float*)d_in[1];
    const float* w1g = (const float*)d_in[2];
    const float* b1g = (const float*)d_in[3];
    const float* w2g = (const float*)d_in[4];
    const float* b2g = (const float*)d_in[5];
    const float* w1f = (const float*)d_in[6];
    const float* b1f = (const float*)d_in[7];
    const float* w2f = (const float*)d_in[8];
    const float* b2f = (const float*)d_in[9];
    float* out = (float*)d_out;

    cudaFuncSetAttribute(gemm_kernel, cudaFuncAttributeMaxDynamicSharedMemorySize,
                         GSMEM_BYTES);

    knn_kernel<<<1536, 256>>>(x, pos);                                    // 0
    buildS_kernel<<<NND + 64, 128>>>(x, pos, w1g, b1g, w2g, 0);           // 1
    buildS_kernel<<<NND + 64, 128>>>(x, pos, w1f, b1f, w2f, 1);           // 2
    gemm_kernel<<<dim3(NND / MT, 2, KSPL), 256, GSMEM_BYTES>>>();         // 3 <- profiled
    combine_kernel<<<NND / 4, 256>>>(b2g, b2f, out);                      // 4
}

// round 15
// speedup vs baseline: 1.2464x; 1.0308x over previous
#include <cuda_runtime.h>
#include <cuda_fp16.h>
#include <math.h>
#include <string.h>
#include <stdint.h>

#define NND   4096
#define KNBR  9
#define INC   32
#define OUTC  64
#define HID   128
#define SDIM  4096
#define KSPL  4
#define KLEN  (SDIM / KSPL)   // 1024
#define KC    64
#define AST   72              // gemm smem row stride (halves)
#define MT    64              // gemm node tile
#define AST2  40              // knn fp16 row stride (halves): conflict-free ldmatrix

// ---------------- scratch (static device globals; no allocation) ----------------
__device__ float g_pd[2][8][NND][KNBR];
__device__ int   g_pi[2][8][NND][KNBR];
__device__ __half g_Xh[NND * INC];               // x hi fp16
__device__ __half g_Xl[NND * INC];               // x lo fp16
__device__ float g_sqx[NND];
__device__ __half g_Sf[2][(size_t)NND * SDIM];   // fp16 S
__device__ __half g_Wt[2][OUTC * SDIM];          // W^T [o][k] fp16
__device__ float g_xjm[2][NND * INC];
__device__ float g_part[2][KSPL][NND][OUTC];

// ======================= KNN helpers ===========================================
__device__ __forceinline__ bool knn_less(float d, int i, float d2, int i2) {
    return (d < d2) || (d == d2 && i < i2);
}
__device__ __forceinline__ void knn_insert(float dist, int j, float bd[KNBR], int bi[KNBR]) {
    if (knn_less(dist, j, bd[KNBR - 1], bi[KNBR - 1])) {
        float cd = dist; int ci = j;
#pragma unroll
        for (int r = 0; r < KNBR; r++) {
            bool sw = knn_less(cd, ci, bd[r], bi[r]);
            float td = bd[r]; int ti = bi[r];
            if (sw) { bd[r] = cd; bi[r] = ci; cd = td; ci = ti; }
        }
    }
}
__device__ __forceinline__ void knn_merge_warp(float* md, int* mi, const float bd[KNBR],
                                               const int bi[KNBR], int lane,
                                               float* opd, int* opi, int q) {
#pragma unroll
    for (int r = 0; r < KNBR; r++) { md[lane * KNBR + r] = bd[r]; mi[lane * KNBR + r] = bi[r]; }
    __syncwarp();
    int p = 0;
    for (int r = 0; r < KNBR; r++) {
        float cd = (p < KNBR) ? md[lane * KNBR + p] : 3.4e38f;
        int   ci = (p < KNBR) ? mi[lane * KNBR + p] : 0x7FFFFFFF;
        float rd = cd; int ri = ci;
#pragma unroll
        for (int off = 16; off; off >>= 1) {
            float od = __shfl_xor_sync(0xFFFFFFFFu, rd, off);
            int   oi = __shfl_xor_sync(0xFFFFFFFFu, ri, off);
            if (knn_less(od, oi, rd, ri)) { rd = od; ri = oi; }
        }
        if (ci == ri && p < KNBR) p++;
        if (lane == 0) { opd[q * KNBR + r] = rd; opi[q * KNBR + r] = ri; }
    }
    __syncwarp();
}

// ================= prep: x -> fp16 hi/lo + fp32 sq-norms =======================
__global__ __launch_bounds__(256) void prep_kernel(const float* __restrict__ x) {
    int i = blockIdx.x * 256 + threadIdx.x;   // 0..131071
    float v = x[i];
    __half h = __float2half_rn(v);
    g_Xh[i] = h;
    g_Xl[i] = __float2half_rn(v - __half2float(h));
    if (i < NND) {
        float s = 0.f;
#pragma unroll
        for (int d = 0; d < INC; d++) { float u = x[i * INC + d]; s = fmaf(u, u, s); }
        g_sqx[i] = s;
    }
}

// ================= mma / ldmatrix helpers ======================================
__device__ __forceinline__ void mma_f16(float* c, const uint32_t* a, const uint32_t* b) {
    asm volatile(
        "mma.sync.aligned.m16n8k16.row.col.f32.f16.f16.f32 "
        "{%0,%1,%2,%3}, {%4,%5,%6,%7}, {%8,%9}, {%0,%1,%2,%3};"
        : "+f"(c[0]), "+f"(c[1]), "+f"(c[2]), "+f"(c[3])
        : "r"(a[0]), "r"(a[1]), "r"(a[2]), "r"(a[3]), "r"(b[0]), "r"(b[1]));
}
__device__ __forceinline__ void ldsm_x4(uint32_t& r0, uint32_t& r1, uint32_t& r2,
                                        uint32_t& r3, uint32_t addr) {
    asm volatile("ldmatrix.sync.aligned.m8n8.x4.shared.b16 {%0,%1,%2,%3}, [%4];"
                 : "=r"(r0), "=r"(r1), "=r"(r2), "=r"(r3) : "r"(addr));
}
__device__ __forceinline__ void cp16(uint32_t dst, const void* src) {
    asm volatile("cp.async.ca.shared.global [%0], [%1], 16;" :: "r"(dst), "l"(src));
}
#define CP_COMMIT() asm volatile("cp.async.commit_group;" ::: "memory")
#define CP_WAIT1()  asm volatile("cp.async.wait_group 1;" ::: "memory")
#define CP_WAIT0()  asm volatile("cp.async.wait_group 0;" ::: "memory")

// ------- fused KNN: blocks [0,512) = feat (4 parts, mma), [512,1536) = pos -----
#define CT 128
#define FPARTS 4
#define FPART2 (NND / FPARTS)   // 1024
#define PPART  (NND / 2)

struct FeatS {
    __half qh[32 * AST2];    // 2560 B
    __half ql[32 * AST2];    // 2560 B
    __half ch[128 * AST2];   // 10240 B  (D + merge buffers aliased onto ch+cl)
    __half cl[128 * AST2];   // 10240 B
    float sqq[32];
    float sqc[CT];
};
#define SMBUF_BYTES 26432

__global__ __launch_bounds__(256) void knn_kernel(const float* __restrict__ x,
                                                  const float* __restrict__ pos) {
    __shared__ __align__(16) char smbuf[SMBUF_BYTES];
    int tid = threadIdx.x, lane = tid & 31, w = tid >> 5;
    int id = blockIdx.x;

    if (id < 512) {
        // ======================= feat branch (tensor-core phase A) =============
        FeatS* fs = reinterpret_cast<FeatS*>(smbuf);
        int bx = id >> 2, part = id & 3;
        int q0 = bx * 32;
        int base0 = part * FPART2;
        int qi = ((tid >> 5) << 2) + (lane >> 3);    // phase-B query (4 per warp)
        int sub = lane & 7;

        const uint4* XhU = reinterpret_cast<const uint4*>(g_Xh);
        const uint4* XlU = reinterpret_cast<const uint4*>(g_Xl);

        // stage queries (32 rows x 4 units, hi/lo)
        for (int v = tid; v < 128; v += 256) {
            int q = v >> 2, j = v & 3;
            *reinterpret_cast<uint4*>(&fs->qh[q * AST2 + j * 8]) = XhU[(q0 + q) * 4 + j];
            *reinterpret_cast<uint4*>(&fs->ql[q * AST2 + j * 8]) = XlU[(q0 + q) * 4 + j];
        }
        if (tid < 32) fs->sqq[tid] = g_sqx[q0 + tid];

        uint32_t chB = (uint32_t)__cvta_generic_to_shared(fs->ch);
        uint32_t clB = (uint32_t)__cvta_generic_to_shared(fs->cl);
        uint32_t qhB = (uint32_t)__cvta_generic_to_shared(fs->qh);
        uint32_t qlB = (uint32_t)__cvta_generic_to_shared(fs->ql);
        float* D = reinterpret_cast<float*>(fs->ch);

        int aRow = (lane & 7) + ((lane >> 3) & 1) * 8;
        int aK   = (lane >> 4) * 8;
        int bRow = ((lane >> 4) * 8) + (lane & 7);
        int bK   = ((lane >> 3) & 1) * 8;
        int g = lane >> 2, t4 = lane & 3;

        float bd[KNBR]; int bi[KNBR];
#pragma unroll
        for (int r = 0; r < KNBR; r++) { bd[r] = 3.4e38f; bi[r] = 0x7FFFFFFF; }

        for (int tile = 0; tile < FPART2 / CT; tile++) {
            int base = base0 + tile * CT;
            __syncthreads();   // prior phase B / D use done
            for (int v = tid; v < 512; v += 256) {
                int c = v >> 2, j = v & 3;
                *reinterpret_cast<uint4*>(&fs->ch[c * AST2 + j * 8]) = XhU[(base + c) * 4 + j];
                *reinterpret_cast<uint4*>(&fs->cl[c * AST2 + j * 8]) = XlU[(base + c) * 4 + j];
            }
            if (tid < CT) fs->sqc[tid] = g_sqx[base + tid];
            __syncthreads();

            // mma: warp w owns cand rows [w*16, w*16+16), all 32 queries
            float acc[4][4];
#pragma unroll
            for (int ni = 0; ni < 4; ni++)
#pragma unroll
                for (int e = 0; e < 4; e++) acc[ni][e] = 0.f;

#pragma unroll
            for (int ks = 0; ks < 2; ks++) {
                int k0 = ks * 16;
                uint32_t Ah4[4], Al4[4], Bh4[4][2], Bl4[4][2];
                uint32_t ao = ((w * 16 + aRow) * AST2 + k0 + aK) * 2;
                ldsm_x4(Ah4[0], Ah4[1], Ah4[2], Ah4[3], chB + ao);
                ldsm_x4(Al4[0], Al4[1], Al4[2], Al4[3], clB + ao);
#pragma unroll
                for (int np = 0; np < 2; np++) {
                    uint32_t bo = ((np * 16 + bRow) * AST2 + k0 + bK) * 2;
                    ldsm_x4(Bh4[2 * np][0], Bh4[2 * np][1],
                            Bh4[2 * np + 1][0], Bh4[2 * np + 1][1], qhB + bo);
                    ldsm_x4(Bl4[2 * np][0], Bl4[2 * np][1],
                            Bl4[2 * np + 1][0], Bl4[2 * np + 1][1], qlB + bo);
                }
#pragma unroll
                for (int ni = 0; ni < 4; ni++) {
                    mma_f16(acc[ni], Ah4, Bh4[ni]);
                    mma_f16(acc[ni], Ah4, Bl4[ni]);
                    mma_f16(acc[ni], Al4, Bh4[ni]);
                }
            }
            __syncthreads();   // ldsm reads done -> overwrite ch/cl with D

            int c0 = w * 16 + g, c1 = c0 + 8;
            float sc0 = fs->sqc[c0], sc1 = fs->sqc[c1];
#pragma unroll
            for (int ni = 0; ni < 4; ni++) {
                int q = ni * 8 + 2 * t4;
                float sq0 = fs->sqq[q], sq1 = fs->sqq[q + 1];
                D[q * 136 + c0]       = (sq0 + sc0) - 2.0f * acc[ni][0];
                D[(q + 1) * 136 + c0] = (sq1 + sc0) - 2.0f * acc[ni][1];
                D[q * 136 + c1]       = (sq0 + sc1) - 2.0f * acc[ni][2];
                D[(q + 1) * 136 + c1] = (sq1 + sc1) - 2.0f * acc[ni][3];
            }
            __syncthreads();

            // phase B: 8 lanes per query, float4 scan, disjoint subsets
#pragma unroll
            for (int t2 = 0; t2 < 4; t2++) {
                int c = t2 * 32 + sub * 4;
                float4 dv = *reinterpret_cast<const float4*>(&D[qi * 136 + c]);
                knn_insert(dv.x, base + c + 0, bd, bi);
                knn_insert(dv.y, base + c + 1, bd, bi);
                knn_insert(dv.z, base + c + 2, bd, bi);
                knn_insert(dv.w, base + c + 3, bd, bi);
            }
        }
        __syncthreads();   // done; overlay merge buffers on ch/cl region

        float* md = reinterpret_cast<float*>(fs->ch);
        int*   mi = reinterpret_cast<int*>(md + 2304);
#pragma unroll
        for (int r = 0; r < KNBR; r++) { md[tid * KNBR + r] = bd[r]; mi[tid * KNBR + r] = bi[r]; }
        __syncwarp();
        int p = 0;
        for (int r = 0; r < KNBR; r++) {
            float cd = (p < KNBR) ? md[tid * KNBR + p] : 3.4e38f;
            int   ci = (p < KNBR) ? mi[tid * KNBR + p] : 0x7FFFFFFF;
            float rd = cd; int ri = ci;
#pragma unroll
            for (int off = 4; off; off >>= 1) {
                float od = __shfl_xor_sync(0xFFFFFFFFu, rd, off);
                int   oi = __shfl_xor_sync(0xFFFFFFFFu, ri, off);
                if (knn_less(od, oi, rd, ri)) { rd = od; ri = oi; }
            }
            if (ci == ri && p < KNBR) p++;
            if (sub == 0) {
                g_pd[1][part][q0 + qi][r] = rd;
                g_pi[1][part][q0 + qi][r] = ri;
            }
        }
    } else {
        // ======================= pos branch (unchanged) ========================
        float* psm = reinterpret_cast<float*>(smbuf);
        int id2 = id - 512;
        int bx = id2 & 511, part = id2 >> 9;
        int q = bx * 8 + w;
        int base = part * PPART;

        for (int v = tid; v < PPART * 3; v += 256) psm[v] = pos[base * 3 + v];
        __syncthreads();

        float q0 = pos[q * 3 + 0], q1 = pos[q * 3 + 1], q2 = pos[q * 3 + 2];
        float sqq = 0.f;
        sqq = fmaf(q0, q0, sqq); sqq = fmaf(q1, q1, sqq); sqq = fmaf(q2, q2, sqq);

        float bd[KNBR]; int bi[KNBR];
#pragma unroll
        for (int r = 0; r < KNBR; r++) { bd[r] = 3.4e38f; bi[r] = 0x7FFFFFFF; }

        for (int jl = lane; jl < PPART; jl += 128) {
            float dist[4];
#pragma unroll
            for (int u = 0; u < 4; u++) {
                int jj = jl + u * 32;
                float c0 = psm[jj * 3 + 0], c1 = psm[jj * 3 + 1], c2 = psm[jj * 3 + 2];
                float acc = 0.f;
                acc = fmaf(q0, c0, acc); acc = fmaf(q1, c1, acc); acc = fmaf(q2, c2, acc);
                float sqj = 0.f;
                sqj = fmaf(c0, c0, sqj); sqj = fmaf(c1, c1, sqj); sqj = fmaf(c2, c2, sqj);
                dist[u] = (sqq + sqj) - 2.0f * acc;
            }
#pragma unroll
            for (int u = 0; u < 4; u++) knn_insert(dist[u], base + jl + u * 32, bd, bi);
        }
        __syncthreads();

        float* md = psm + (size_t)w * 288;
        int*   mi = (int*)(psm + 8 * 288) + (size_t)w * 288;
        knn_merge_warp(md, mi, bd, bi, lane, &g_pd[0][part][0][0], &g_pi[0][part][0][0], q);
    }
}

// ====== buildS (inline P-way merge) + transposeW side-blocks, per branch =======
__global__ __launch_bounds__(128) void buildS_kernel(
    const float* __restrict__ x, const float* __restrict__ pos,
    const float* __restrict__ w1, const float* __restrict__ b1,
    const float* __restrict__ w2, int br) {
    int t = threadIdx.x;

    if (blockIdx.x >= NND) {
        __shared__ float tile[64][65];
        int kt = blockIdx.x - NND;
        for (int v = t; v < 64 * 64; v += 128) {
            int kk = v >> 6, o = v & 63;
            tile[kk][o] = w2[(size_t)(kt * 64 + kk) * 64 + o];
        }
        __syncthreads();
        for (int v = t; v < 64 * 64; v += 128) {
            int o = v >> 6, kk = v & 63;
            g_Wt[br][(size_t)o * SDIM + kt * 64 + kk] = __float2half_rn(tile[kk][o]);
        }
        return;
    }

    int n = blockIdx.x;
    __shared__ int   s_idx[KNBR];
    __shared__ float s_xj[KNBR][INC];
    __shared__ float s_attr[KNBR][3];
    __shared__ float s_h[KNBR][HID];
    __shared__ float s_pn[3];

    if (t == 0) {
        int P = br ? FPARTS : 2;
        int p[8];
#pragma unroll
        for (int u = 0; u < 8; u++) p[u] = 0;
        for (int r = 0; r < KNBR; r++) {
            float bdv = 3.4e38f; int biv = 0x7FFFFFFF, bt = 0;
            for (int u = 0; u < P; u++) {
                float d = g_pd[br][u][n][p[u]];
                int   i = g_pi[br][u][n][p[u]];
                if (knn_less(d, i, bdv, biv)) { bdv = d; biv = i; bt = u; }
            }
            p[bt]++;
            s_idx[r] = biv;
        }
    }
    if (t < 3) s_pn[t] = pos[n * 3 + t];
    __syncthreads();

    for (int v = t; v < KNBR * INC; v += 128)
        s_xj[v / INC][v % INC] = x[(size_t)s_idx[v / INC] * INC + (v % INC)];

    if (t < KNBR) {
        int sj = s_idx[t];
        float cx = pos[sj * 3 + 0] - s_pn[0];
        float cy = pos[sj * 3 + 1] - s_pn[1];
        float cz = pos[sj * 3 + 2] - s_pn[2];
        float rho = sqrtf((cx * cx + cy * cy) + cz * cz);
        float th  = atan2f(cy, cx);
        float ratio = cz / fmaxf(rho, 1e-12f);
        ratio = fminf(1.0f, fmaxf(-1.0f, ratio));
        float ph = acosf(ratio);
        s_attr[t][0] = rho; s_attr[t][1] = th; s_attr[t][2] = ph;
    }
    __syncthreads();

    {
        int c = t;
        float wa = w1[c], wb = w1[HID + c], wc = w1[2 * HID + c], bb = b1[c];
        float hk[KNBR];
#pragma unroll
        for (int k = 0; k < KNBR; k++)
            hk[k] = tanhf(bb + s_attr[k][0] * wa + s_attr[k][1] * wb + s_attr[k][2] * wc);
#pragma unroll
        for (int k = 0; k < KNBR; k++) s_h[k][c] = hk[k];
    }
    __syncthreads();

    int w = t >> 5, lane = t & 31;
    int i0 = (lane & 15) * 2;
    float xjr0[KNBR], xjr1[KNBR];
#pragma unroll
    for (int k = 0; k < KNBR; k++) { xjr0[k] = s_xj[k][i0]; xjr1[k] = s_xj[k][i0 + 1]; }

    __half2* Sf2 = reinterpret_cast<__half2*>(g_Sf[br] + (size_t)n * SDIM);
#pragma unroll
    for (int j = 0; j < 16; j++) {
        int c = w * 32 + 2 * j + (lane >> 4);
        float s0 = 0.f, s1 = 0.f;
#pragma unroll
        for (int k = 0; k < KNBR; k++) {
            float hv = s_h[k][c];
            s0 = fmaf(hv, xjr0[k], s0);
            s1 = fmaf(hv, xjr1[k], s1);
        }
        Sf2[c * 16 + (lane & 15)] = __halves2half2(__float2half_rn(s0), __float2half_rn(s1));
    }
    if (t < INC) {
        float m = 0.f;
#pragma unroll
        for (int k = 0; k < KNBR; k++) m += s_xj[k][t];
        g_xjm[br][n * INC + t] = m * (1.0f / 9.0f);
    }
}

// ================= GEMM: cp.async double-buffered, mma f16 (single W) ==========
#define STAGE_BYTES (2 * 64 * AST * 2)   // 18432 B
#define GSMEM_BYTES (2 * STAGE_BYTES)    // 36864 B

__global__ __launch_bounds__(256, 4) void gemm_kernel() {
    extern __shared__ __align__(16) __half sm[];

    int tid = threadIdx.x, warp = tid >> 5, lane = tid & 31;
    int br = blockIdx.y, kz = blockIdx.z;
    int n0 = blockIdx.x * MT;
    int kbase = kz * KLEN;
    int mw = warp & 1, nw = warp >> 1;
    int g = lane >> 2, t = lane & 3;

    const __half* SfG = g_Sf[br];
    const __half* WG  = g_Wt[br];

    uint32_t smBase = (uint32_t)__cvta_generic_to_shared(sm);
    int am = tid >> 3, aj = tid & 7;

    auto issue_stage = [&](int st, int koff) {
        uint32_t base = smBase + st * STAGE_BYTES;
#pragma unroll
        for (int h = 0; h < 2; h++) {
            int m = am + h * 32;
            cp16(base + (m * AST + aj * 8) * 2,
                 SfG + (size_t)(n0 + m) * SDIM + koff + aj * 8);
        }
#pragma unroll
        for (int h = 0; h < 2; h++) {
            int o = am + h * 32;
            cp16(base + 9216 + (o * AST + aj * 8) * 2,
                 WG + (size_t)o * SDIM + koff + aj * 8);
        }
        CP_COMMIT();
    };

    int aRow = (lane & 7) + ((lane >> 3) & 1) * 8;
    int aK   = (lane >> 4) * 8;
    int bRow = ((lane >> 4) * 8) + (lane & 7);
    int bK   = ((lane >> 3) & 1) * 8;

    float acc[2][2][4];
#pragma unroll
    for (int mi = 0; mi < 2; mi++)
#pragma unroll
        for (int ni = 0; ni < 2; ni++)
#pragma unroll
            for (int e = 0; e < 4; e++) acc[mi][ni][e] = 0.f;

    const int NCH = KLEN / KC;
    issue_stage(0, kbase);

    for (int c = 0; c < NCH; c++) {
        int st = c & 1;
        __syncthreads();
        if (c + 1 < NCH) issue_stage((c + 1) & 1, kbase + (c + 1) * KC);
        if (c + 1 < NCH) { CP_WAIT1(); } else { CP_WAIT0(); }
        __syncthreads();

        uint32_t base = smBase + st * STAGE_BYTES;
#pragma unroll
        for (int ks = 0; ks < KC / 16; ks++) {
            int k0 = ks * 16;
            uint32_t ah[2][4], bh[2][2];
#pragma unroll
            for (int mi = 0; mi < 2; mi++) {
                uint32_t ao = ((mw * 32 + mi * 16 + aRow) * AST + k0 + aK) * 2;
                ldsm_x4(ah[mi][0], ah[mi][1], ah[mi][2], ah[mi][3], base + ao);
            }
            {
                uint32_t bo = ((nw * 16 + bRow) * AST + k0 + bK) * 2;
                ldsm_x4(bh[0][0], bh[0][1], bh[1][0], bh[1][1], base + 9216 + bo);
            }
#pragma unroll
            for (int mi = 0; mi < 2; mi++)
#pragma unroll
                for (int ni = 0; ni < 2; ni++)
                    mma_f16(acc[mi][ni], ah[mi], bh[ni]);
        }
    }

    float* P = &g_part[br][kz][0][0];
#pragma unroll
    for (int mi = 0; mi < 2; mi++) {
        int r0 = n0 + mw * 32 + mi * 16;
#pragma unroll
        for (int ni = 0; ni < 2; ni++) {
            int col = nw * 16 + ni * 8 + 2 * t;
            float2 v01 = make_float2(acc[mi][ni][0], acc[mi][ni][1]);
            float2 v23 = make_float2(acc[mi][ni][2], acc[mi][ni][3]);
            *reinterpret_cast<float2*>(&P[(size_t)(r0 + g) * OUTC + col]) = v01;
            *reinterpret_cast<float2*>(&P[(size_t)(r0 + g + 8) * OUTC + col]) = v23;
        }
    }
}

// ================= combine: out = 0.5*((sum parts)/9 + xm@b2 both) =============
__global__ __launch_bounds__(256) void combine_kernel(
    const float* __restrict__ b2g, const float* __restrict__ b2f,
    float* __restrict__ out) {
    __shared__ float s_b2[2][INC * OUTC];
    __shared__ float s_xm[2][4][INC];

    int tid = threadIdx.x;
    int nl = tid >> 6, o = tid & 63;
    int n = blockIdx.x * 4 + nl;

    for (int v = tid; v < INC * OUTC; v += 256) {
        s_b2[0][v] = b2g[v];
        s_b2[1][v] = b2f[v];
    }
    {
        int br = tid >> 7, nn = (tid >> 5) & 3, i = tid & 31;
        s_xm[br][nn][i] = g_xjm[br][(size_t)(blockIdx.x * 4 + nn) * INC + i];
    }
    __syncthreads();

    float val = 0.f;
#pragma unroll
    for (int br = 0; br < 2; br++)
#pragma unroll
        for (int kzi = 0; kzi < KSPL; kzi++)
            val += g_part[br][kzi][n][o];
    val *= (1.0f / 9.0f);
#pragma unroll
    for (int br = 0; br < 2; br++)
#pragma unroll
        for (int i = 0; i < INC; i++)
            val = fmaf(s_xm[br][nl][i], s_b2[br][i * OUTC + o], val);
    out[(size_t)n * OUTC + o] = 0.5f * val;
}

// ---------------- launch -------------------------------------------------------
extern "C" void kernel_launch(void* const* d_in, const int* in_sizes, int n_in,
                              void* d_out, int out_size) {
    const float* x   = (const float*)d_in[0];
    const float* pos = (const float*)d_in[1];
    const float* w1g = (const float*)d_in[2];
    const float* b1g = (const float*)d_in[3];
    const float* w2g = (const float*)d_in[4];
    const float* b2g = (const float*)d_in[5];
    const float* w1f = (const float*)d_in[6];
    const float* b1f = (const float*)d_in[7];
    const float* w2f = (const float*)d_in[8];
    const float* b2f = (const float*)d_in[9];
    float* out = (float*)d_out;

    cudaFuncSetAttribute(gemm_kernel, cudaFuncAttributeMaxDynamicSharedMemorySize,
                         GSMEM_BYTES);

    prep_kernel<<<NND * INC / 256, 256>>>(x);                             // 0
    knn_kernel<<<1536, 256>>>(x, pos);                                    // 1
    buildS_kernel<<<NND + 64, 128>>>(x, pos, w1g, b1g, w2g, 0);           // 2
    buildS_kernel<<<NND + 64, 128>>>(x, pos, w1f, b1f, w2f, 1);           // 3 <- profiled
    gemm_kernel<<<dim3(NND / MT, 2, KSPL), 256, GSMEM_BYTES>>>();         // 4
    combine_kernel<<<NND / 4, 256>>>(b2g, b2f, out);                      // 5
}

// round 16
// speedup vs baseline: 1.2682x; 1.0175x over previous
#include <cuda_runtime.h>
#include <cuda_fp16.h>
#include <math.h>
#include <string.h>
#include <stdint.h>

#define NND   4096
#define KNBR  9
#define INC   32
#define OUTC  64
#define HID   128
#define SDIM  4096
#define KSPL  4
#define KLEN  (SDIM / KSPL)   // 1024
#define KC    64
#define AST   72              // gemm smem row stride (halves)
#define MT    64              // gemm node tile
#define AST2  40              // knn fp16 row stride (halves)

// ---------------- scratch (static device globals; no allocation) ----------------
__device__ float g_pd[2][8][NND][KNBR];
__device__ int   g_pi[2][8][NND][KNBR];
__device__ __half g_Xh[NND * INC];
__device__ __half g_Xl[NND * INC];
__device__ float g_sqx[NND];
__device__ __half g_Sf[2][(size_t)NND * SDIM];
__device__ __half g_Wt[2][OUTC * SDIM];
__device__ float g_xjm[2][NND * INC];
__device__ float g_part[2][KSPL][NND][OUTC];

// ======================= KNN helpers ===========================================
__device__ __forceinline__ bool knn_less(float d, int i, float d2, int i2) {
    return (d < d2) || (d == d2 && i < i2);
}
__device__ __forceinline__ void knn_insert(float dist, int j, float bd[KNBR], int bi[KNBR]) {
    if (knn_less(dist, j, bd[KNBR - 1], bi[KNBR - 1])) {
        float cd = dist; int ci = j;
#pragma unroll
        for (int r = 0; r < KNBR; r++) {
            bool sw = knn_less(cd, ci, bd[r], bi[r]);
            float td = bd[r]; int ti = bi[r];
            if (sw) { bd[r] = cd; bi[r] = ci; cd = td; ci = ti; }
        }
    }
}
__device__ __forceinline__ void knn_merge_warp(float* md, int* mi, const float bd[KNBR],
                                               const int bi[KNBR], int lane,
                                               float* opd, int* opi, int q) {
#pragma unroll
    for (int r = 0; r < KNBR; r++) { md[lane * KNBR + r] = bd[r]; mi[lane * KNBR + r] = bi[r]; }
    __syncwarp();
    int p = 0;
    for (int r = 0; r < KNBR; r++) {
        float cd = (p < KNBR) ? md[lane * KNBR + p] : 3.4e38f;
        int   ci = (p < KNBR) ? mi[lane * KNBR + p] : 0x7FFFFFFF;
        float rd = cd; int ri = ci;
#pragma unroll
        for (int off = 16; off; off >>= 1) {
            float od = __shfl_xor_sync(0xFFFFFFFFu, rd, off);
            int   oi = __shfl_xor_sync(0xFFFFFFFFu, ri, off);
            if (knn_less(od, oi, rd, ri)) { rd = od; ri = oi; }
        }
        if (ci == ri && p < KNBR) p++;
        if (lane == 0) { opd[q * KNBR + r] = rd; opi[q * KNBR + r] = ri; }
    }
    __syncwarp();
}

// ================= prep: x -> fp16 hi/lo ; sq: fp32 norms ======================
__global__ __launch_bounds__(256) void prep_kernel(const float* __restrict__ x) {
    int i = blockIdx.x * 256 + threadIdx.x;
    float v = x[i];
    __half h = __float2half_rn(v);
    g_Xh[i] = h;
    g_Xl[i] = __float2half_rn(v - __half2float(h));
}
__global__ __launch_bounds__(256) void sq_kernel(const float* __restrict__ x) {
    int i = blockIdx.x * 256 + threadIdx.x;
    float s = 0.f;
#pragma unroll
    for (int d = 0; d < INC; d++) { float u = x[i * INC + d]; s = fmaf(u, u, s); }
    g_sqx[i] = s;
}

// ================= transposeW: w2 [k][o] fp32 -> W^T [o][k] fp16 ===============
__global__ __launch_bounds__(128) void transposeW_kernel(
    const float* __restrict__ w2g, const float* __restrict__ w2f) {
    __shared__ float tile[64][65];
    int t = threadIdx.x;
    int kt = blockIdx.x, br = blockIdx.y;
    const float* w2 = br ? w2f : w2g;
    for (int v = t; v < 64 * 64; v += 128) {
        int kk = v >> 6, o = v & 63;
        tile[kk][o] = w2[(size_t)(kt * 64 + kk) * 64 + o];
    }
    __syncthreads();
    for (int v = t; v < 64 * 64; v += 128) {
        int o = v >> 6, kk = v & 63;
        g_Wt[br][(size_t)o * SDIM + kt * 64 + kk] = __float2half_rn(tile[kk][o]);
    }
}

// ================= mma / ldmatrix / cp.async helpers ===========================
__device__ __forceinline__ void mma_f16(float* c, const uint32_t* a, const uint32_t* b) {
    asm volatile(
        "mma.sync.aligned.m16n8k16.row.col.f32.f16.f16.f32 "
        "{%0,%1,%2,%3}, {%4,%5,%6,%7}, {%8,%9}, {%0,%1,%2,%3};"
        : "+f"(c[0]), "+f"(c[1]), "+f"(c[2]), "+f"(c[3])
        : "r"(a[0]), "r"(a[1]), "r"(a[2]), "r"(a[3]), "r"(b[0]), "r"(b[1]));
}
__device__ __forceinline__ void ldsm_x4(uint32_t& r0, uint32_t& r1, uint32_t& r2,
                                        uint32_t& r3, uint32_t addr) {
    asm volatile("ldmatrix.sync.aligned.m8n8.x4.shared.b16 {%0,%1,%2,%3}, [%4];"
                 : "=r"(r0), "=r"(r1), "=r"(r2), "=r"(r3) : "r"(addr));
}
__device__ __forceinline__ void cp16(uint32_t dst, const void* src) {
    asm volatile("cp.async.ca.shared.global [%0], [%1], 16;" :: "r"(dst), "l"(src));
}
#define CP_COMMIT() asm volatile("cp.async.commit_group;" ::: "memory")
#define CP_WAIT1()  asm volatile("cp.async.wait_group 1;" ::: "memory")
#define CP_WAIT0()  asm volatile("cp.async.wait_group 0;" ::: "memory")

// ------- fused KNN: blocks [0,512) = feat (4 parts, mma), [512,1536) = pos -----
#define CT 128
#define FPARTS 4
#define FPART2 (NND / FPARTS)   // 1024
#define PPART  (NND / 2)

struct FeatS {
    __half qh[32 * AST2];
    __half ql[32 * AST2];
    __half ch[128 * AST2];
    __half cl[128 * AST2];
    float sqq[32];
    float sqc[CT];
};
#define SMBUF_BYTES 26432

__global__ __launch_bounds__(256) void knn_kernel(const float* __restrict__ x,
                                                  const float* __restrict__ pos) {
    __shared__ __align__(16) char smbuf[SMBUF_BYTES];
    int tid = threadIdx.x, lane = tid & 31, w = tid >> 5;
    int id = blockIdx.x;

    if (id < 512) {
        // ======================= feat branch (tensor-core phase A) =============
        FeatS* fs = reinterpret_cast<FeatS*>(smbuf);
        int bx = id >> 2, part = id & 3;
        int q0 = bx * 32;
        int base0 = part * FPART2;
        int qi = ((tid >> 5) << 2) + (lane >> 3);
        int sub = lane & 7;

        const uint4* XhU = reinterpret_cast<const uint4*>(g_Xh);
        const uint4* XlU = reinterpret_cast<const uint4*>(g_Xl);

        for (int v = tid; v < 128; v += 256) {
            int q = v >> 2, j = v & 3;
            *reinterpret_cast<uint4*>(&fs->qh[q * AST2 + j * 8]) = XhU[(q0 + q) * 4 + j];
            *reinterpret_cast<uint4*>(&fs->ql[q * AST2 + j * 8]) = XlU[(q0 + q) * 4 + j];
        }
        if (tid < 32) fs->sqq[tid] = g_sqx[q0 + tid];

        uint32_t chB = (uint32_t)__cvta_generic_to_shared(fs->ch);
        uint32_t clB = (uint32_t)__cvta_generic_to_shared(fs->cl);
        uint32_t qhB = (uint32_t)__cvta_generic_to_shared(fs->qh);
        uint32_t qlB = (uint32_t)__cvta_generic_to_shared(fs->ql);
        float* D = reinterpret_cast<float*>(fs->ch);

        int aRow = (lane & 7) + ((lane >> 3) & 1) * 8;
        int aK   = (lane >> 4) * 8;
        int bRow = ((lane >> 4) * 8) + (lane & 7);
        int bK   = ((lane >> 3) & 1) * 8;
        int g = lane >> 2, t4 = lane & 3;

        float bd[KNBR]; int bi[KNBR];
#pragma unroll
        for (int r = 0; r < KNBR; r++) { bd[r] = 3.4e38f; bi[r] = 0x7FFFFFFF; }

        for (int tile = 0; tile < FPART2 / CT; tile++) {
            int base = base0 + tile * CT;
            __syncthreads();
            for (int v = tid; v < 512; v += 256) {
                int c = v >> 2, j = v & 3;
                *reinterpret_cast<uint4*>(&fs->ch[c * AST2 + j * 8]) = XhU[(base + c) * 4 + j];
                *reinterpret_cast<uint4*>(&fs->cl[c * AST2 + j * 8]) = XlU[(base + c) * 4 + j];
            }
            if (tid < CT) fs->sqc[tid] = g_sqx[base + tid];
            __syncthreads();

            float acc[4][4];
#pragma unroll
            for (int ni = 0; ni < 4; ni++)
#pragma unroll
                for (int e = 0; e < 4; e++) acc[ni][e] = 0.f;

#pragma unroll
            for (int ks = 0; ks < 2; ks++) {
                int k0 = ks * 16;
                uint32_t Ah4[4], Al4[4], Bh4[4][2], Bl4[4][2];
                uint32_t ao = ((w * 16 + aRow) * AST2 + k0 + aK) * 2;
                ldsm_x4(Ah4[0], Ah4[1], Ah4[2], Ah4[3], chB + ao);
                ldsm_x4(Al4[0], Al4[1], Al4[2], Al4[3], clB + ao);
#pragma unroll
                for (int np = 0; np < 2; np++) {
                    uint32_t bo = ((np * 16 + bRow) * AST2 + k0 + bK) * 2;
                    ldsm_x4(Bh4[2 * np][0], Bh4[2 * np][1],
                            Bh4[2 * np + 1][0], Bh4[2 * np + 1][1], qhB + bo);
                    ldsm_x4(Bl4[2 * np][0], Bl4[2 * np][1],
                            Bl4[2 * np + 1][0], Bl4[2 * np + 1][1], qlB + bo);
                }
#pragma unroll
                for (int ni = 0; ni < 4; ni++) {
                    mma_f16(acc[ni], Ah4, Bh4[ni]);
                    mma_f16(acc[ni], Ah4, Bl4[ni]);
                    mma_f16(acc[ni], Al4, Bh4[ni]);
                }
            }
            __syncthreads();

            int c0 = w * 16 + g, c1 = c0 + 8;
            float sc0 = fs->sqc[c0], sc1 = fs->sqc[c1];
#pragma unroll
            for (int ni = 0; ni < 4; ni++) {
                int q = ni * 8 + 2 * t4;
                float sq0 = fs->sqq[q], sq1 = fs->sqq[q + 1];
                D[q * 136 + c0]       = (sq0 + sc0) - 2.0f * acc[ni][0];
                D[(q + 1) * 136 + c0] = (sq1 + sc0) - 2.0f * acc[ni][1];
                D[q * 136 + c1]       = (sq0 + sc1) - 2.0f * acc[ni][2];
                D[(q + 1) * 136 + c1] = (sq1 + sc1) - 2.0f * acc[ni][3];
            }
            __syncthreads();

#pragma unroll
            for (int t2 = 0; t2 < 4; t2++) {
                int c = t2 * 32 + sub * 4;
                float4 dv = *reinterpret_cast<const float4*>(&D[qi * 136 + c]);
                knn_insert(dv.x, base + c + 0, bd, bi);
                knn_insert(dv.y, base + c + 1, bd, bi);
                knn_insert(dv.z, base + c + 2, bd, bi);
                knn_insert(dv.w, base + c + 3, bd, bi);
            }
        }
        __syncthreads();

        float* md = reinterpret_cast<float*>(fs->ch);
        int*   mi = reinterpret_cast<int*>(md + 2304);
#pragma unroll
        for (int r = 0; r < KNBR; r++) { md[tid * KNBR + r] = bd[r]; mi[tid * KNBR + r] = bi[r]; }
        __syncwarp();
        int p = 0;
        for (int r = 0; r < KNBR; r++) {
            float cd = (p < KNBR) ? md[tid * KNBR + p] : 3.4e38f;
            int   ci = (p < KNBR) ? mi[tid * KNBR + p] : 0x7FFFFFFF;
            float rd = cd; int ri = ci;
#pragma unroll
            for (int off = 4; off; off >>= 1) {
                float od = __shfl_xor_sync(0xFFFFFFFFu, rd, off);
                int   oi = __shfl_xor_sync(0xFFFFFFFFu, ri, off);
                if (knn_less(od, oi, rd, ri)) { rd = od; ri = oi; }
            }
            if (ci == ri && p < KNBR) p++;
            if (sub == 0) {
                g_pd[1][part][q0 + qi][r] = rd;
                g_pi[1][part][q0 + qi][r] = ri;
            }
        }
    } else {
        // ======================= pos branch ====================================
        float* psm = reinterpret_cast<float*>(smbuf);
        int id2 = id - 512;
        int bx = id2 & 511, part = id2 >> 9;
        int q = bx * 8 + w;
        int base = part * PPART;

        for (int v = tid; v < PPART * 3; v += 256) psm[v] = pos[base * 3 + v];
        __syncthreads();

        float q0 = pos[q * 3 + 0], q1 = pos[q * 3 + 1], q2 = pos[q * 3 + 2];
        float sqq = 0.f;
        sqq = fmaf(q0, q0, sqq); sqq = fmaf(q1, q1, sqq); sqq = fmaf(q2, q2, sqq);

        float bd[KNBR]; int bi[KNBR];
#pragma unroll
        for (int r = 0; r < KNBR; r++) { bd[r] = 3.4e38f; bi[r] = 0x7FFFFFFF; }

        for (int jl = lane; jl < PPART; jl += 128) {
            float dist[4];
#pragma unroll
            for (int u = 0; u < 4; u++) {
                int jj = jl + u * 32;
                float c0 = psm[jj * 3 + 0], c1 = psm[jj * 3 + 1], c2 = psm[jj * 3 + 2];
                float acc = 0.f;
                acc = fmaf(q0, c0, acc); acc = fmaf(q1, c1, acc); acc = fmaf(q2, c2, acc);
                float sqj = 0.f;
                sqj = fmaf(c0, c0, sqj); sqj = fmaf(c1, c1, sqj); sqj = fmaf(c2, c2, sqj);
                dist[u] = (sqq + sqj) - 2.0f * acc;
            }
#pragma unroll
            for (int u = 0; u < 4; u++) knn_insert(dist[u], base + jl + u * 32, bd, bi);
        }
        __syncthreads();

        float* md = psm + (size_t)w * 288;
        int*   mi = (int*)(psm + 8 * 288) + (size_t)w * 288;
        knn_merge_warp(md, mi, bd, bi, lane, &g_pd[0][part][0][0], &g_pi[0][part][0][0], q);
    }
}

// ====== buildS: fused branches (grid (NND, 2)), inline P-way merge =============
__global__ __launch_bounds__(128) void buildS_kernel(
    const float* __restrict__ x, const float* __restrict__ pos,
    const float* __restrict__ w1g, const float* __restrict__ b1g,
    const float* __restrict__ w1f, const float* __restrict__ b1f) {
    int t = threadIdx.x;
    int n = blockIdx.x, br = blockIdx.y;
    const float* w1 = br ? w1f : w1g;
    const float* b1 = br ? b1f : b1g;

    __shared__ int   s_idx[KNBR];
    __shared__ float s_xj[KNBR][INC];
    __shared__ float s_attr[KNBR][3];
    __shared__ float s_h[KNBR][HID];
    __shared__ float s_pn[3];

    if (t == 0) {
        int P = br ? FPARTS : 2;
        int p[8];
#pragma unroll
        for (int u = 0; u < 8; u++) p[u] = 0;
        for (int r = 0; r < KNBR; r++) {
            float bdv = 3.4e38f; int biv = 0x7FFFFFFF, bt = 0;
            for (int u = 0; u < P; u++) {
                float d = g_pd[br][u][n][p[u]];
                int   i = g_pi[br][u][n][p[u]];
                if (knn_less(d, i, bdv, biv)) { bdv = d; biv = i; bt = u; }
            }
            p[bt]++;
            s_idx[r] = biv;
        }
    }
    if (t < 3) s_pn[t] = pos[n * 3 + t];
    __syncthreads();

    for (int v = t; v < KNBR * INC; v += 128)
        s_xj[v / INC][v % INC] = x[(size_t)s_idx[v / INC] * INC + (v % INC)];

    if (t < KNBR) {
        int sj = s_idx[t];
        float cx = pos[sj * 3 + 0] - s_pn[0];
        float cy = pos[sj * 3 + 1] - s_pn[1];
        float cz = pos[sj * 3 + 2] - s_pn[2];
        float rho = sqrtf((cx * cx + cy * cy) + cz * cz);
        float th  = atan2f(cy, cx);
        float ratio = cz / fmaxf(rho, 1e-12f);
        ratio = fminf(1.0f, fmaxf(-1.0f, ratio));
        float ph = acosf(ratio);
        s_attr[t][0] = rho; s_attr[t][1] = th; s_attr[t][2] = ph;
    }
    __syncthreads();

    {
        int c = t;
        float wa = w1[c], wb = w1[HID + c], wc = w1[2 * HID + c], bb = b1[c];
        float hk[KNBR];
#pragma unroll
        for (int k = 0; k < KNBR; k++)
            hk[k] = tanhf(bb + s_attr[k][0] * wa + s_attr[k][1] * wb + s_attr[k][2] * wc);
#pragma unroll
        for (int k = 0; k < KNBR; k++) s_h[k][c] = hk[k];
    }
    __syncthreads();

    int w = t >> 5, lane = t & 31;
    int i0 = (lane & 15) * 2;
    float xjr0[KNBR], xjr1[KNBR];
#pragma unroll
    for (int k = 0; k < KNBR; k++) { xjr0[k] = s_xj[k][i0]; xjr1[k] = s_xj[k][i0 + 1]; }

    __half2* Sf2 = reinterpret_cast<__half2*>(g_Sf[br] + (size_t)n * SDIM);
#pragma unroll
    for (int j = 0; j < 16; j++) {
        int c = w * 32 + 2 * j + (lane >> 4);
        float s0 = 0.f, s1 = 0.f;
#pragma unroll
        for (int k = 0; k < KNBR; k++) {
            float hv = s_h[k][c];
            s0 = fmaf(hv, xjr0[k], s0);
            s1 = fmaf(hv, xjr1[k], s1);
        }
        Sf2[c * 16 + (lane & 15)] = __halves2half2(__float2half_rn(s0), __float2half_rn(s1));
    }
    if (t < INC) {
        float m = 0.f;
#pragma unroll
        for (int k = 0; k < KNBR; k++) m += s_xj[k][t];
        g_xjm[br][n * INC + t] = m * (1.0f / 9.0f);
    }
}

// ================= GEMM: cp.async double-buffered, mma f16 (single W) ==========
#define STAGE_BYTES (2 * 64 * AST * 2)   // 18432 B
#define GSMEM_BYTES (2 * STAGE_BYTES)    // 36864 B

__global__ __launch_bounds__(256, 4) void gemm_kernel() {
    extern __shared__ __align__(16) __half sm[];

    int tid = threadIdx.x, warp = tid >> 5, lane = tid & 31;
    int br = blockIdx.y, kz = blockIdx.z;
    int n0 = blockIdx.x * MT;
    int kbase = kz * KLEN;
    int mw = warp & 1, nw = warp >> 1;
    int g = lane >> 2, t = lane & 3;

    const __half* SfG = g_Sf[br];
    const __half* WG  = g_Wt[br];

    uint32_t smBase = (uint32_t)__cvta_generic_to_shared(sm);
    int am = tid >> 3, aj = tid & 7;

    auto issue_stage = [&](int st, int koff) {
        uint32_t base = smBase + st * STAGE_BYTES;
#pragma unroll
        for (int h = 0; h < 2; h++) {
            int m = am + h * 32;
            cp16(base + (m * AST + aj * 8) * 2,
                 SfG + (size_t)(n0 + m) * SDIM + koff + aj * 8);
        }
#pragma unroll
        for (int h = 0; h < 2; h++) {
            int o = am + h * 32;
            cp16(base + 9216 + (o * AST + aj * 8) * 2,
                 WG + (size_t)o * SDIM + koff + aj * 8);
        }
        CP_COMMIT();
    };

    int aRow = (lane & 7) + ((lane >> 3) & 1) * 8;
    int aK   = (lane >> 4) * 8;
    int bRow = ((lane >> 4) * 8) + (lane & 7);
    int bK   = ((lane >> 3) & 1) * 8;

    float acc[2][2][4];
#pragma unroll
    for (int mi = 0; mi < 2; mi++)
#pragma unroll
        for (int ni = 0; ni < 2; ni++)
#pragma unroll
            for (int e = 0; e < 4; e++) acc[mi][ni][e] = 0.f;

    const int NCH = KLEN / KC;
    issue_stage(0, kbase);

    for (int c = 0; c < NCH; c++) {
        int st = c & 1;
        __syncthreads();
        if (c + 1 < NCH) issue_stage((c + 1) & 1, kbase + (c + 1) * KC);
        if (c + 1 < NCH) { CP_WAIT1(); } else { CP_WAIT0(); }
        __syncthreads();

        uint32_t base = smBase + st * STAGE_BYTES;
#pragma unroll
        for (int ks = 0; ks < KC / 16; ks++) {
            int k0 = ks * 16;
            uint32_t ah[2][4], bh[2][2];
#pragma unroll
            for (int mi = 0; mi < 2; mi++) {
                uint32_t ao = ((mw * 32 + mi * 16 + aRow) * AST + k0 + aK) * 2;
                ldsm_x4(ah[mi][0], ah[mi][1], ah[mi][2], ah[mi][3], base + ao);
            }
            {
                uint32_t bo = ((nw * 16 + bRow) * AST + k0 + bK) * 2;
                ldsm_x4(bh[0][0], bh[0][1], bh[1][0], bh[1][1], base + 9216 + bo);
            }
#pragma unroll
            for (int mi = 0; mi < 2; mi++)
#pragma unroll
                for (int ni = 0; ni < 2; ni++)
                    mma_f16(acc[mi][ni], ah[mi], bh[ni]);
        }
    }

    float* P = &g_part[br][kz][0][0];
#pragma unroll
    for (int mi = 0; mi < 2; mi++) {
        int r0 = n0 + mw * 32 + mi * 16;
#pragma unroll
        for (int ni = 0; ni < 2; ni++) {
            int col = nw * 16 + ni * 8 + 2 * t;
            float2 v01 = make_float2(acc[mi][ni][0], acc[mi][ni][1]);
            float2 v23 = make_float2(acc[mi][ni][2], acc[mi][ni][3]);
            *reinterpret_cast<float2*>(&P[(size_t)(r0 + g) * OUTC + col]) = v01;
            *reinterpret_cast<float2*>(&P[(size_t)(r0 + g + 8) * OUTC + col]) = v23;
        }
    }
}

// ================= combine: out = 0.5*((sum parts)/9 + xm@b2 both) =============
__global__ __launch_bounds__(256) void combine_kernel(
    const float* __restrict__ b2g, const float* __restrict__ b2f,
    float* __restrict__ out) {
    __shared__ float s_b2[2][INC * OUTC];
    __shared__ float s_xm[2][4][INC];

    int tid = threadIdx.x;
    int nl = tid >> 6, o = tid & 63;
    int n = blockIdx.x * 4 + nl;

    for (int v = tid; v < INC * OUTC; v += 256) {
        s_b2[0][v] = b2g[v];
        s_b2[1][v] = b2f[v];
    }
    {
        int br = tid >> 7, nn = (tid >> 5) & 3, i = tid & 31;
        s_xm[br][nn][i] = g_xjm[br][(size_t)(blockIdx.x * 4 + nn) * INC + i];
    }
    __syncthreads();

    float val = 0.f;
#pragma unroll
    for (int br = 0; br < 2; br++)
#pragma unroll
        for (int kzi = 0; kzi < KSPL; kzi++)
            val += g_part[br][kzi][n][o];
    val *= (1.0f / 9.0f);
#pragma unroll
    for (int br = 0; br < 2; br++)
#pragma unroll
        for (int i = 0; i < INC; i++)
            val = fmaf(s_xm[br][nl][i], s_b2[br][i * OUTC + o], val);
    out[(size_t)n * OUTC + o] = 0.5f * val;
}

// ---------------- launch -------------------------------------------------------
extern "C" void kernel_launch(void* const* d_in, const int* in_sizes, int n_in,
                              void* d_out, int out_size) {
    const float* x   = (const float*)d_in[0];
    const float* pos = (const float*)d_in[1];
    const float* w1g = (const float*)d_in[2];
    const float* b1g = (const float*)d_in[3];
    const float* w2g = (const float*)d_in[4];
    const float* b2g = (const float*)d_in[5];
    const float* w1f = (const float*)d_in[6];
    const float* b1f = (const float*)d_in[7];
    const float* w2f = (const float*)d_in[8];
    const float* b2f = (const float*)d_in[9];
    float* out = (float*)d_out;

    cudaFuncSetAttribute(gemm_kernel, cudaFuncAttributeMaxDynamicSharedMemorySize,
                         GSMEM_BYTES);

    prep_kernel<<<NND * INC / 256, 256>>>(x);                             // 0
    sq_kernel<<<NND / 256, 256>>>(x);                                     // 1
    transposeW_kernel<<<dim3(SDIM / 64, 2), 128>>>(w2g, w2f);             // 2
    knn_kernel<<<1536, 256>>>(x, pos);                                    // 3 <- profiled
    buildS_kernel<<<dim3(NND, 2), 128>>>(x, pos, w1g, b1g, w1f, b1f);     // 4
    gemm_kernel<<<dim3(NND / MT, 2, KSPL), 256, GSMEM_BYTES>>>();         // 5
    combine_kernel<<<NND / 4, 256>>>(b2g, b2f, out);                      // 6
}

// round 17
// speedup vs baseline: 1.4921x; 1.1766x over previous
#include <cuda_runtime.h>
#include <cuda_fp16.h>
#include <math.h>
#include <string.h>
#include <stdint.h>

#define NND   4096
#define KNBR  9
#define INC   32
#define OUTC  64
#define HID   128
#define SDIM  4096
#define KSPL  4
#define KLEN  (SDIM / KSPL)   // 1024
#define KC    64
#define AST   72              // gemm smem row stride (halves)
#define MT    64              // gemm node tile
#define AST2  40              // knn fp16 row stride (halves)

// ---------------- scratch (static device globals; no allocation) ----------------
__device__ unsigned long long g_pk[2][8][NND][KNBR];   // packed (dist,idx) keys
__device__ __half g_Xh[NND * INC];
__device__ __half g_Xl[NND * INC];
__device__ float g_sqx[NND];
__device__ __half g_Sf[2][(size_t)NND * SDIM];
__device__ __half g_Wt[2][OUTC * SDIM];
__device__ float g_xjm[2][NND * INC];
__device__ float g_part[2][KSPL][NND][OUTC];

// ======================= KNN key helpers =======================================
// Exact order-preserving pack: (dist asc, idx asc)  <=>  u64 key asc.
// ordered_int: flip sign bit for positives, flip all bits for negatives.
__device__ __forceinline__ unsigned long long dkey(float d, int j) {
    uint32_t b = __float_as_uint(d);
    b ^= (b & 0x80000000u) ? 0xFFFFFFFFu : 0x80000000u;
    return ((unsigned long long)b << 32) | (uint32_t)j;
}
#define KMAX 0xFFFFFFFFFFFFFFFFull

__device__ __forceinline__ void kinsert(unsigned long long k, unsigned long long bk[KNBR]) {
    if (k < bk[KNBR - 1]) {
#pragma unroll
        for (int r = 0; r < KNBR; r++) {
            bool sw = k < bk[r];
            unsigned long long t = bk[r];
            bk[r] = sw ? k : bk[r];
            k = sw ? t : k;
        }
    }
}

// warp-wide 9-round merge of per-lane sorted key lists (32-lane)
__device__ __forceinline__ void kmerge_warp(unsigned long long* mk,
                                            const unsigned long long bk[KNBR],
                                            int lane, unsigned long long* opk, int q) {
#pragma unroll
    for (int r = 0; r < KNBR; r++) mk[lane * KNBR + r] = bk[r];
    __syncwarp();
    int p = 0;
    for (int r = 0; r < KNBR; r++) {
        unsigned long long ck = (p < KNBR) ? mk[lane * KNBR + p] : KMAX;
        unsigned long long rk = ck;
#pragma unroll
        for (int off = 16; off; off >>= 1) {
            unsigned long long ok = __shfl_xor_sync(0xFFFFFFFFu, rk, off);
            rk = (ok < rk) ? ok : rk;
        }
        if (ck == rk && p < KNBR) p++;   // keys unique (idx embedded)
        if (lane == 0) opk[q * KNBR + r] = rk;
    }
    __syncwarp();
}

// ================= prep: x -> fp16 hi/lo ; sq: fp32 norms ======================
__global__ __launch_bounds__(256) void prep_kernel(const float* __restrict__ x) {
    int i = blockIdx.x * 256 + threadIdx.x;
    float v = x[i];
    __half h = __float2half_rn(v);
    g_Xh[i] = h;
    g_Xl[i] = __float2half_rn(v - __half2float(h));
}
__global__ __launch_bounds__(256) void sq_kernel(const float* __restrict__ x) {
    int i = blockIdx.x * 256 + threadIdx.x;
    float s = 0.f;
#pragma unroll
    for (int d = 0; d < INC; d++) { float u = x[i * INC + d]; s = fmaf(u, u, s); }
    g_sqx[i] = s;
}

// ================= transposeW: w2 [k][o] fp32 -> W^T [o][k] fp16 ===============
__global__ __launch_bounds__(128) void transposeW_kernel(
    const float* __restrict__ w2g, const float* __restrict__ w2f) {
    __shared__ float tile[64][65];
    int t = threadIdx.x;
    int kt = blockIdx.x, br = blockIdx.y;
    const float* w2 = br ? w2f : w2g;
    for (int v = t; v < 64 * 64; v += 128) {
        int kk = v >> 6, o = v & 63;
        tile[kk][o] = w2[(size_t)(kt * 64 + kk) * 64 + o];
    }
    __syncthreads();
    for (int v = t; v < 64 * 64; v += 128) {
        int o = v >> 6, kk = v & 63;
        g_Wt[br][(size_t)o * SDIM + kt * 64 + kk] = __float2half_rn(tile[kk][o]);
    }
}

// ================= mma / ldmatrix / cp.async helpers ===========================
__device__ __forceinline__ void mma_f16(float* c, const uint32_t* a, const uint32_t* b) {
    asm volatile(
        "mma.sync.aligned.m16n8k16.row.col.f32.f16.f16.f32 "
        "{%0,%1,%2,%3}, {%4,%5,%6,%7}, {%8,%9}, {%0,%1,%2,%3};"
        : "+f"(c[0]), "+f"(c[1]), "+f"(c[2]), "+f"(c[3])
        : "r"(a[0]), "r"(a[1]), "r"(a[2]), "r"(a[3]), "r"(b[0]), "r"(b[1]));
}
__device__ __forceinline__ void ldsm_x4(uint32_t& r0, uint32_t& r1, uint32_t& r2,
                                        uint32_t& r3, uint32_t addr) {
    asm volatile("ldmatrix.sync.aligned.m8n8.x4.shared.b16 {%0,%1,%2,%3}, [%4];"
                 : "=r"(r0), "=r"(r1), "=r"(r2), "=r"(r3) : "r"(addr));
}
__device__ __forceinline__ void cp16(uint32_t dst, const void* src) {
    asm volatile("cp.async.ca.shared.global [%0], [%1], 16;" :: "r"(dst), "l"(src));
}
#define CP_COMMIT() asm volatile("cp.async.commit_group;" ::: "memory")
#define CP_WAIT1()  asm volatile("cp.async.wait_group 1;" ::: "memory")
#define CP_WAIT0()  asm volatile("cp.async.wait_group 0;" ::: "memory")

// ------- fused KNN: blocks [0,512) = feat (4 parts, mma), [512,1536) = pos -----
#define CT 128
#define FPARTS 4
#define FPART2 (NND / FPARTS)   // 1024
#define PPART  (NND / 2)

struct FeatS {
    __half qh[32 * AST2];
    __half ql[32 * AST2];
    __half ch[128 * AST2];
    __half cl[128 * AST2];
    float sqq[32];
    float sqc[CT];
};
#define SMBUF_BYTES 26432

__global__ __launch_bounds__(256) void knn_kernel(const float* __restrict__ x,
                                                  const float* __restrict__ pos) {
    __shared__ __align__(16) char smbuf[SMBUF_BYTES];
    int tid = threadIdx.x, lane = tid & 31, w = tid >> 5;
    int id = blockIdx.x;

    if (id < 512) {
        // ======================= feat branch (tensor-core phase A) =============
        FeatS* fs = reinterpret_cast<FeatS*>(smbuf);
        int bx = id >> 2, part = id & 3;
        int q0 = bx * 32;
        int base0 = part * FPART2;
        int qi = ((tid >> 5) << 2) + (lane >> 3);
        int sub = lane & 7;

        const uint4* XhU = reinterpret_cast<const uint4*>(g_Xh);
        const uint4* XlU = reinterpret_cast<const uint4*>(g_Xl);

        for (int v = tid; v < 128; v += 256) {
            int q = v >> 2, j = v & 3;
            *reinterpret_cast<uint4*>(&fs->qh[q * AST2 + j * 8]) = XhU[(q0 + q) * 4 + j];
            *reinterpret_cast<uint4*>(&fs->ql[q * AST2 + j * 8]) = XlU[(q0 + q) * 4 + j];
        }
        if (tid < 32) fs->sqq[tid] = g_sqx[q0 + tid];

        uint32_t chB = (uint32_t)__cvta_generic_to_shared(fs->ch);
        uint32_t clB = (uint32_t)__cvta_generic_to_shared(fs->cl);
        uint32_t qhB = (uint32_t)__cvta_generic_to_shared(fs->qh);
        uint32_t qlB = (uint32_t)__cvta_generic_to_shared(fs->ql);
        float* D = reinterpret_cast<float*>(fs->ch);

        int aRow = (lane & 7) + ((lane >> 3) & 1) * 8;
        int aK   = (lane >> 4) * 8;
        int bRow = ((lane >> 4) * 8) + (lane & 7);
        int bK   = ((lane >> 3) & 1) * 8;
        int g = lane >> 2, t4 = lane & 3;

        unsigned long long bk[KNBR];
#pragma unroll
        for (int r = 0; r < KNBR; r++) bk[r] = KMAX;

        for (int tile = 0; tile < FPART2 / CT; tile++) {
            int base = base0 + tile * CT;
            __syncthreads();
            for (int v = tid; v < 512; v += 256) {
                int c = v >> 2, j = v & 3;
                *reinterpret_cast<uint4*>(&fs->ch[c * AST2 + j * 8]) = XhU[(base + c) * 4 + j];
                *reinterpret_cast<uint4*>(&fs->cl[c * AST2 + j * 8]) = XlU[(base + c) * 4 + j];
            }
            if (tid < CT) fs->sqc[tid] = g_sqx[base + tid];
            __syncthreads();

            float acc[4][4];
#pragma unroll
            for (int ni = 0; ni < 4; ni++)
#pragma unroll
                for (int e = 0; e < 4; e++) acc[ni][e] = 0.f;

#pragma unroll
            for (int ks = 0; ks < 2; ks++) {
                int k0 = ks * 16;
                uint32_t Ah4[4], Al4[4], Bh4[4][2], Bl4[4][2];
                uint32_t ao = ((w * 16 + aRow) * AST2 + k0 + aK) * 2;
                ldsm_x4(Ah4[0], Ah4[1], Ah4[2], Ah4[3], chB + ao);
                ldsm_x4(Al4[0], Al4[1], Al4[2], Al4[3], clB + ao);
#pragma unroll
                for (int np = 0; np < 2; np++) {
                    uint32_t bo = ((np * 16 + bRow) * AST2 + k0 + bK) * 2;
                    ldsm_x4(Bh4[2 * np][0], Bh4[2 * np][1],
                            Bh4[2 * np + 1][0], Bh4[2 * np + 1][1], qhB + bo);
                    ldsm_x4(Bl4[2 * np][0], Bl4[2 * np][1],
                            Bl4[2 * np + 1][0], Bl4[2 * np + 1][1], qlB + bo);
                }
#pragma unroll
                for (int ni = 0; ni < 4; ni++) {
                    mma_f16(acc[ni], Ah4, Bh4[ni]);
                    mma_f16(acc[ni], Ah4, Bl4[ni]);
                    mma_f16(acc[ni], Al4, Bh4[ni]);
                }
            }
            __syncthreads();

            int c0 = w * 16 + g, c1 = c0 + 8;
            float sc0 = fs->sqc[c0], sc1 = fs->sqc[c1];
#pragma unroll
            for (int ni = 0; ni < 4; ni++) {
                int q = ni * 8 + 2 * t4;
                float sq0 = fs->sqq[q], sq1 = fs->sqq[q + 1];
                D[q * 136 + c0]       = (sq0 + sc0) - 2.0f * acc[ni][0];
                D[(q + 1) * 136 + c0] = (sq1 + sc0) - 2.0f * acc[ni][1];
                D[q * 136 + c1]       = (sq0 + sc1) - 2.0f * acc[ni][2];
                D[(q + 1) * 136 + c1] = (sq1 + sc1) - 2.0f * acc[ni][3];
            }
            __syncthreads();

#pragma unroll
            for (int t2 = 0; t2 < 4; t2++) {
                int c = t2 * 32 + sub * 4;
                float4 dv = *reinterpret_cast<const float4*>(&D[qi * 136 + c]);
                kinsert(dkey(dv.x, base + c + 0), bk);
                kinsert(dkey(dv.y, base + c + 1), bk);
                kinsert(dkey(dv.z, base + c + 2), bk);
                kinsert(dkey(dv.w, base + c + 3), bk);
            }
        }
        __syncthreads();

        // exact 8-lane merge per query (u64 keys)
        unsigned long long* mk = reinterpret_cast<unsigned long long*>(fs->ch);
#pragma unroll
        for (int r = 0; r < KNBR; r++) mk[tid * KNBR + r] = bk[r];
        __syncwarp();
        int p = 0;
        for (int r = 0; r < KNBR; r++) {
            unsigned long long ck = (p < KNBR) ? mk[tid * KNBR + p] : KMAX;
            unsigned long long rk = ck;
#pragma unroll
            for (int off = 4; off; off >>= 1) {
                unsigned long long ok = __shfl_xor_sync(0xFFFFFFFFu, rk, off);
                rk = (ok < rk) ? ok : rk;
            }
            if (ck == rk && p < KNBR) p++;
            if (sub == 0) g_pk[1][part][q0 + qi][r] = rk;
        }
    } else {
        // ======================= pos branch ====================================
        float* psm = reinterpret_cast<float*>(smbuf);
        int id2 = id - 512;
        int bx = id2 & 511, part = id2 >> 9;
        int q = bx * 8 + w;
        int base = part * PPART;

        for (int v = tid; v < PPART * 3; v += 256) psm[v] = pos[base * 3 + v];
        __syncthreads();

        float q0 = pos[q * 3 + 0], q1 = pos[q * 3 + 1], q2 = pos[q * 3 + 2];
        float sqq = 0.f;
        sqq = fmaf(q0, q0, sqq); sqq = fmaf(q1, q1, sqq); sqq = fmaf(q2, q2, sqq);

        unsigned long long bk[KNBR];
#pragma unroll
        for (int r = 0; r < KNBR; r++) bk[r] = KMAX;

        for (int jl = lane; jl < PPART; jl += 128) {
            float dist[4];
#pragma unroll
            for (int u = 0; u < 4; u++) {
                int jj = jl + u * 32;
                float c0 = psm[jj * 3 + 0], c1 = psm[jj * 3 + 1], c2 = psm[jj * 3 + 2];
                float acc = 0.f;
                acc = fmaf(q0, c0, acc); acc = fmaf(q1, c1, acc); acc = fmaf(q2, c2, acc);
                float sqj = 0.f;
                sqj = fmaf(c0, c0, sqj); sqj = fmaf(c1, c1, sqj); sqj = fmaf(c2, c2, sqj);
                dist[u] = (sqq + sqj) - 2.0f * acc;
            }
#pragma unroll
            for (int u = 0; u < 4; u++) kinsert(dkey(dist[u], base + jl + u * 32), bk);
        }
        __syncthreads();

        unsigned long long* mk =
            reinterpret_cast<unsigned long long*>(psm) + (size_t)w * 288;
        kmerge_warp(mk, bk, lane, &g_pk[0][part][0][0], q);
    }
}

// ====== buildS: fused branches (grid (NND, 2)), inline P-way key merge =========
__global__ __launch_bounds__(128) void buildS_kernel(
    const float* __restrict__ x, const float* __restrict__ pos,
    const float* __restrict__ w1g, const float* __restrict__ b1g,
    const float* __restrict__ w1f, const float* __restrict__ b1f) {
    int t = threadIdx.x;
    int n = blockIdx.x, br = blockIdx.y;
    const float* w1 = br ? w1f : w1g;
    const float* b1 = br ? b1f : b1g;

    __shared__ int   s_idx[KNBR];
    __shared__ float s_xj[KNBR][INC];
    __shared__ float s_attr[KNBR][3];
    __shared__ float s_h[KNBR][HID];
    __shared__ float s_pn[3];

    if (t == 0) {
        int P = br ? FPARTS : 2;
        int p[8];
#pragma unroll
        for (int u = 0; u < 8; u++) p[u] = 0;
        for (int r = 0; r < KNBR; r++) {
            unsigned long long bkv = KMAX; int bt = 0;
            for (int u = 0; u < P; u++) {
                unsigned long long k = g_pk[br][u][n][p[u]];
                if (k < bkv) { bkv = k; bt = u; }
            }
            p[bt]++;
            s_idx[r] = (int)(bkv & 0xFFFFFFFFull);
        }
    }
    if (t < 3) s_pn[t] = pos[n * 3 + t];
    __syncthreads();

    for (int v = t; v < KNBR * INC; v += 128)
        s_xj[v / INC][v % INC] = x[(size_t)s_idx[v / INC] * INC + (v % INC)];

    if (t < KNBR) {
        int sj = s_idx[t];
        float cx = pos[sj * 3 + 0] - s_pn[0];
        float cy = pos[sj * 3 + 1] - s_pn[1];
        float cz = pos[sj * 3 + 2] - s_pn[2];
        float rho = sqrtf((cx * cx + cy * cy) + cz * cz);
        float th  = atan2f(cy, cx);
        float ratio = cz / fmaxf(rho, 1e-12f);
        ratio = fminf(1.0f, fmaxf(-1.0f, ratio));
        float ph = acosf(ratio);
        s_attr[t][0] = rho; s_attr[t][1] = th; s_attr[t][2] = ph;
    }
    __syncthreads();

    {
        int c = t;
        float wa = w1[c], wb = w1[HID + c], wc = w1[2 * HID + c], bb = b1[c];
        float hk[KNBR];
#pragma unroll
        for (int k = 0; k < KNBR; k++)
            hk[k] = tanhf(bb + s_attr[k][0] * wa + s_attr[k][1] * wb + s_attr[k][2] * wc);
#pragma unroll
        for (int k = 0; k < KNBR; k++) s_h[k][c] = hk[k];
    }
    __syncthreads();

    int w = t >> 5, lane = t & 31;
    int i0 = (lane & 15) * 2;
    float xjr0[KNBR], xjr1[KNBR];
#pragma unroll
    for (int k = 0; k < KNBR; k++) { xjr0[k] = s_xj[k][i0]; xjr1[k] = s_xj[k][i0 + 1]; }

    __half2* Sf2 = reinterpret_cast<__half2*>(g_Sf[br] + (size_t)n * SDIM);
#pragma unroll
    for (int j = 0; j < 16; j++) {
        int c = w * 32 + 2 * j + (lane >> 4);
        float s0 = 0.f, s1 = 0.f;
#pragma unroll
        for (int k = 0; k < KNBR; k++) {
            float hv = s_h[k][c];
            s0 = fmaf(hv, xjr0[k], s0);
            s1 = fmaf(hv, xjr1[k], s1);
        }
        Sf2[c * 16 + (lane & 15)] = __halves2half2(__float2half_rn(s0), __float2half_rn(s1));
    }
    if (t < INC) {
        float m = 0.f;
#pragma unroll
        for (int k = 0; k < KNBR; k++) m += s_xj[k][t];
        g_xjm[br][n * INC + t] = m * (1.0f / 9.0f);
    }
}

// ================= GEMM: cp.async double-buffered, mma f16 (single W) ==========
#define STAGE_BYTES (2 * 64 * AST * 2)   // 18432 B
#define GSMEM_BYTES (2 * STAGE_BYTES)    // 36864 B

__global__ __launch_bounds__(256, 4) void gemm_kernel() {
    extern __shared__ __align__(16) __half sm[];

    int tid = threadIdx.x, warp = tid >> 5, lane = tid & 31;
    int br = blockIdx.y, kz = blockIdx.z;
    int n0 = blockIdx.x * MT;
    int kbase = kz * KLEN;
    int mw = warp & 1, nw = warp >> 1;
    int g = lane >> 2, t = lane & 3;

    const __half* SfG = g_Sf[br];
    const __half* WG  = g_Wt[br];

    uint32_t smBase = (uint32_t)__cvta_generic_to_shared(sm);
    int am = tid >> 3, aj = tid & 7;

    auto issue_stage = [&](int st, int koff) {
        uint32_t base = smBase + st * STAGE_BYTES;
#pragma unroll
        for (int h = 0; h < 2; h++) {
            int m = am + h * 32;
            cp16(base + (m * AST + aj * 8) * 2,
                 SfG + (size_t)(n0 + m) * SDIM + koff + aj * 8);
        }
#pragma unroll
        for (int h = 0; h < 2; h++) {
            int o = am + h * 32;
            cp16(base + 9216 + (o * AST + aj * 8) * 2,
                 WG + (size_t)o * SDIM + koff + aj * 8);
        }
        CP_COMMIT();
    };

    int aRow = (lane & 7) + ((lane >> 3) & 1) * 8;
    int aK   = (lane >> 4) * 8;
    int bRow = ((lane >> 4) * 8) + (lane & 7);
    int bK   = ((lane >> 3) & 1) * 8;

    float acc[2][2][4];
#pragma unroll
    for (int mi = 0; mi < 2; mi++)
#pragma unroll
        for (int ni = 0; ni < 2; ni++)
#pragma unroll
            for (int e = 0; e < 4; e++) acc[mi][ni][e] = 0.f;

    const int NCH = KLEN / KC;
    issue_stage(0, kbase);

    for (int c = 0; c < NCH; c++) {
        int st = c & 1;
        __syncthreads();
        if (c + 1 < NCH) issue_stage((c + 1) & 1, kbase + (c + 1) * KC);
        if (c + 1 < NCH) { CP_WAIT1(); } else { CP_WAIT0(); }
        __syncthreads();

        uint32_t base = smBase + st * STAGE_BYTES;
#pragma unroll
        for (int ks = 0; ks < KC / 16; ks++) {
            int k0 = ks * 16;
            uint32_t ah[2][4], bh[2][2];
#pragma unroll
            for (int mi = 0; mi < 2; mi++) {
                uint32_t ao = ((mw * 32 + mi * 16 + aRow) * AST + k0 + aK) * 2;
                ldsm_x4(ah[mi][0], ah[mi][1], ah[mi][2], ah[mi][3], base + ao);
            }
            {
                uint32_t bo = ((nw * 16 + bRow) * AST + k0 + bK) * 2;
                ldsm_x4(bh[0][0], bh[0][1], bh[1][0], bh[1][1], base + 9216 + bo);
            }
#pragma unroll
            for (int mi = 0; mi < 2; mi++)
#pragma unroll
                for (int ni = 0; ni < 2; ni++)
                    mma_f16(acc[mi][ni], ah[mi], bh[ni]);
        }
    }

    float* P = &g_part[br][kz][0][0];
#pragma unroll
    for (int mi = 0; mi < 2; mi++) {
        int r0 = n0 + mw * 32 + mi * 16;
#pragma unroll
        for (int ni = 0; ni < 2; ni++) {
            int col = nw * 16 + ni * 8 + 2 * t;
            float2 v01 = make_float2(acc[mi][ni][0], acc[mi][ni][1]);
            float2 v23 = make_float2(acc[mi][ni][2], acc[mi][ni][3]);
            *reinterpret_cast<float2*>(&P[(size_t)(r0 + g) * OUTC + col]) = v01;
            *reinterpret_cast<float2*>(&P[(size_t)(r0 + g + 8) * OUTC + col]) = v23;
        }
    }
}

// ================= combine: out = 0.5*((sum parts)/9 + xm@b2 both) =============
__global__ __launch_bounds__(256) void combine_kernel(
    const float* __restrict__ b2g, const float* __restrict__ b2f,
    float* __restrict__ out) {
    __shared__ float s_b2[2][INC * OUTC];
    __shared__ float s_xm[2][4][INC];

    int tid = threadIdx.x;
    int nl = tid >> 6, o = tid & 63;
    int n = blockIdx.x * 4 + nl;

    for (int v = tid; v < INC * OUTC; v += 256) {
        s_b2[0][v] = b2g[v];
        s_b2[1][v] = b2f[v];
    }
    {
        int br = tid >> 7, nn = (tid >> 5) & 3, i = tid & 31;
        s_xm[br][nn][i] = g_xjm[br][(size_t)(blockIdx.x * 4 + nn) * INC + i];
    }
    __syncthreads();

    float val = 0.f;
#pragma unroll
    for (int br = 0; br < 2; br++)
#pragma unroll
        for (int kzi = 0; kzi < KSPL; kzi++)
            val += g_part[br][kzi][n][o];
    val *= (1.0f / 9.0f);
#pragma unroll
    for (int br = 0; br < 2; br++)
#pragma unroll
        for (int i = 0; i < INC; i++)
            val = fmaf(s_xm[br][nl][i], s_b2[br][i * OUTC + o], val);
    out[(size_t)n * OUTC + o] = 0.5f * val;
}

// ---------------- launch -------------------------------------------------------
extern "C" void kernel_launch(void* const* d_in, const int* in_sizes, int n_in,
                              void* d_out, int out_size) {
    const float* x   = (const float*)d_in[0];
    const float* pos = (const float*)d_in[1];
    const float* w1g = (const float*)d_in[2];
    const float* b1g = (const float*)d_in[3];
    const float* w2g = (const float*)d_in[4];
    const float* b2g = (const float*)d_in[5];
    const float* w1f = (const float*)d_in[6];
    const float* b1f = (const float*)d_in[7];
    const float* w2f = (const float*)d_in[8];
    const float* b2f = (const float*)d_in[9];
    float* out = (float*)d_out;

    cudaFuncSetAttribute(gemm_kernel, cudaFuncAttributeMaxDynamicSharedMemorySize,
                         GSMEM_BYTES);

    prep_kernel<<<NND * INC / 256, 256>>>(x);                             // 0
    sq_kernel<<<NND / 256, 256>>>(x);                                     // 1
    transposeW_kernel<<<dim3(SDIM / 64, 2), 128>>>(w2g, w2f);             // 2
    knn_kernel<<<1536, 256>>>(x, pos);                                    // 3 <- profiled
    buildS_kernel<<<dim3(NND, 2), 128>>>(x, pos, w1g, b1g, w1f, b1f);     // 4
    gemm_kernel<<<dim3(NND / MT, 2, KSPL), 256, GSMEM_BYTES>>>();         // 5
    combine_kernel<<<NND / 4, 256>>>(b2g, b2f, out);                      // 6
}